// round 10
// baseline (speedup 1.0000x reference)
#include <cuda_runtime.h>
#include <cuda_bf16.h>
#include <math.h>
#include <stdint.h>

#define NN 1024
#define MM 64
#define LDA 1040
#define NTH 512
#define PP 64              // halves pitch of global bf16 panel planes (128B rows)

__device__ float g_cov[(size_t)MM * NN * LDA];
__device__ uint16_t g_pH[(size_t)MM * NN * PP];
__device__ uint16_t g_pL[(size_t)MM * NN * PP];

__device__ __forceinline__ void cluster_sync_() {
    asm volatile("barrier.cluster.arrive.aligned;" ::: "memory");
    asm volatile("barrier.cluster.wait.aligned;" ::: "memory");
}
__device__ __forceinline__ void hmma(float* c, const uint32_t* a, const uint32_t* b) {
    asm volatile("mma.sync.aligned.m16n8k16.row.col.f32.bf16.bf16.f32 "
        "{%0,%1,%2,%3},{%4,%5,%6,%7},{%8,%9},{%0,%1,%2,%3};"
        : "+f"(c[0]), "+f"(c[1]), "+f"(c[2]), "+f"(c[3])
        : "r"(a[0]), "r"(a[1]), "r"(a[2]), "r"(a[3]), "r"(b[0]), "r"(b[1]));
}

__device__ __forceinline__ float sp_(float x) {
    return fmaxf(x, 0.f) + log1pf(expf(-fabsf(x))) + 1e-7f;
}
__device__ __forceinline__ float log_normal_(float v, float mean, float s, float eps) {
    const float C = -0.91893853320467274178f;
    float d = v - mean;
    return -d * d / (2.f * s * s + eps) - logf(s) + C;
}
__device__ __forceinline__ float log_lognormal_(float v, float mean, float s, float eps) {
    const float C = -0.91893853320467274178f;
    float lv = logf(v);
    float d = lv - mean;
    return -d * d / (2.f * s * s + eps) - lv - logf(s) + C;
}
__device__ __forceinline__ void trsm_row(float* a, const float* Lkk, const float* rinv) {
    #pragma unroll
    for (int j = 0; j < 32; ++j) {
        float s = a[j];
        #pragma unroll
        for (int p = 0; p < j; ++p) s -= a[p] * Lkk[j * 33 + p];
        a[j] = s * rinv[j];
    }
}

// store one solved 32-wide row piece into global bf16 hi/lo planes at column base cb
__device__ __forceinline__ void store_row_bf16(uint16_t* H, uint16_t* L, int row, int cb, const float* a) {
    uint32_t hw[16], lw[16];
    #pragma unroll
    for (int q = 0; q < 16; ++q) {
        float f0 = a[2*q], f1 = a[2*q+1];
        __nv_bfloat16 h0 = __float2bfloat16(f0);
        __nv_bfloat16 h1 = __float2bfloat16(f1);
        __nv_bfloat16 l0 = __float2bfloat16(f0 - __bfloat162float(h0));
        __nv_bfloat16 l1 = __float2bfloat16(f1 - __bfloat162float(h1));
        hw[q] = (uint32_t)__bfloat16_as_ushort(h0) | ((uint32_t)__bfloat16_as_ushort(h1) << 16);
        lw[q] = (uint32_t)__bfloat16_as_ushort(l0) | ((uint32_t)__bfloat16_as_ushort(l1) << 16);
    }
    uint32_t* hr = (uint32_t*)(H + (size_t)row * PP + cb);
    uint32_t* lr = (uint32_t*)(L + (size_t)row * PP + cb);
    #pragma unroll
    for (int q = 0; q < 4; ++q) {
        ((uint4*)hr)[q] = make_uint4(hw[4*q], hw[4*q+1], hw[4*q+2], hw[4*q+3]);
        ((uint4*)lr)[q] = make_uint4(lw[4*q], lw[4*q+1], lw[4*q+2], lw[4*q+3]);
    }
}

extern "C" __global__ void __launch_bounds__(NTH, 1) __cluster_dims__(2, 1, 1)
vi_kernel(const float* __restrict__ x, const float* __restrict__ y,
          const float* __restrict__ z,
          const float* qbm, const float* qbs, const float* qsm, const float* qss,
          const float* qem, const float* qes, const float* qzm, const float* qzs,
          const float* qnm, const float* qns, float* __restrict__ out)
{
    __shared__ float xs[2048];       // scaled x (build); rhs (fwd-subst)
    __shared__ float Lkk[32 * 33];
    __shared__ float Bb[32 * 33];
    __shared__ float rinv[32];
    __shared__ float scal[8];
    __shared__ float red[NTH];

    const int tid  = threadIdx.x;
    const int wid  = tid >> 5;
    const int lane = tid & 31;
    const int m    = blockIdx.x >> 1;
    const int rank = blockIdx.x & 1;
    float* cov = g_cov + (size_t)m * NN * LDA;
    uint16_t* gH = g_pH + (size_t)m * NN * PP;
    uint16_t* gL = g_pL + (size_t)m * NN * PP;

    // ---- scalar terms (redundant in both CTAs) ----
    if (tid == 0) {
        float s0 = sp_(sqrtf(logf(2.f)));
        float z0 = z[m*5+0], z1 = z[m*5+1], z2 = z[m*5+2], z3 = z[m*5+3], z4 = z[m*5+4];
        float sps = sp_(*qss), spb = sp_(*qbs), spe = sp_(*qes), spz = sp_(*qzs), spn = sp_(*qns);
        float sigma2 = expf(z0 * sps + *qsm);
        float beta   = z1 * spb + *qbm;
        float eta    = expf(z2 * spe + *qem);
        float lsZ    = expf(z3 * spz + *qzm);
        float lsN    = expf(z4 * spn + *qnm);
        float lp = log_normal_(beta, 0.f, 1.f, 1e-5f)
                 + log_lognormal_(sigma2, 1.f, s0, 1e-6f)
                 + log_lognormal_(eta,    1.f, s0, 1e-6f)
                 + log_lognormal_(lsZ,    1.f, s0, 1e-6f)
                 + log_lognormal_(lsN,    1.f, s0, 1e-6f);
        float lq = log_normal_(beta, *qbm, spb, 1e-5f)
                 + log_lognormal_(sigma2, *qsm, sps, 1e-6f)
                 + log_lognormal_(eta,    *qem, spe, 1e-6f)
                 + log_lognormal_(lsZ,    *qzm, spz, 1e-6f)
                 + log_lognormal_(lsN,    *qnm, spn, 1e-6f);
        scal[0] = beta; scal[1] = sigma2; scal[2] = eta;
        scal[3] = lsZ;  scal[4] = lsN;    scal[5] = lp - lq;
        scal[6] = 0.f;
    }
    __syncthreads();
    const float beta = scal[0], sigma2 = scal[1], eta = scal[2];

    // ---- stage scaled x ----
    {
        float lsZ = scal[3], lsN = scal[4];
        for (int i = tid; i < NN; i += NTH) {
            xs[i]      = x[2 * i]     / lsZ;
            xs[NN + i] = x[2 * i + 1] / lsN;
        }
    }
    __syncthreads();

    // ---- build lower-triangular cov, rows split by parity ----
    {
        const float* xs0 = xs;
        const float* xs1 = xs + NN;
        for (int it = tid; it < NN / 2; it += NTH) {
            int i = 2 * it + rank;
            float xi0 = xs0[i], xi1 = xs1[i];
            float* row = cov + (size_t)i * LDA;
            int j4 = i & ~3;
            for (int j = 0; j < j4; j += 4) {
                float4 a0 = *(const float4*)(xs0 + j);
                float4 a1 = *(const float4*)(xs1 + j);
                float4 o; float d0, d1;
                d0 = xi0 - a0.x; d1 = xi1 - a1.x; o.x = eta * __expf(-0.5f * (d0*d0 + d1*d1));
                d0 = xi0 - a0.y; d1 = xi1 - a1.y; o.y = eta * __expf(-0.5f * (d0*d0 + d1*d1));
                d0 = xi0 - a0.z; d1 = xi1 - a1.z; o.z = eta * __expf(-0.5f * (d0*d0 + d1*d1));
                d0 = xi0 - a0.w; d1 = xi1 - a1.w; o.w = eta * __expf(-0.5f * (d0*d0 + d1*d1));
                *(float4*)(row + j) = o;
            }
            for (int j = j4; j < i; ++j) {
                float d0 = xi0 - xs0[j], d1 = xi1 - xs1[j];
                row[j] = eta * __expf(-0.5f * (d0 * d0 + d1 * d1));
            }
            row[i] = eta + sigma2;
        }
    }
    cluster_sync_();

    // ---- blocked Cholesky: outer NB=64 (16 steps), 2-stage inner panels ----
    for (int kb = 0; kb < 16; ++kb) {
        const int k0 = kb * 64;
        const int R1 = NN - k0 - 32;          // panel1 rows (start k0+32)
        const int nt = NN - k0 - 64;          // trailing size (start k0+64)

        // ===== stage 1: diag1 + panel1 (cols k0..k0+31) =====
        for (int idx = tid; idx < 1024; idx += NTH) {
            int r = idx >> 5, c = idx & 31;
            Lkk[r * 33 + c] = (c <= r) ? cov[(size_t)(k0 + r) * LDA + k0 + c] : 0.f;
        }
        const int h1len = (R1 + 1) >> 1;
        const int h1s = rank * h1len;
        const int h1e = (rank == 0) ? h1len : R1;
        float a1[32];
        const int r1 = h1s + tid - 32;
        const bool pv1 = (tid >= 32) && (r1 < h1e);
        if (pv1) {
            const float* rr = cov + (size_t)(k0 + 32 + r1) * LDA + k0;
            #pragma unroll
            for (int w = 0; w < 8; ++w) {
                float4 q = ((const float4*)rr)[w];
                a1[4*w] = q.x; a1[4*w+1] = q.y; a1[4*w+2] = q.z; a1[4*w+3] = q.w;
            }
        }
        __syncthreads();

        if (tid < 32) {     // factor diag1
            float a[32];
            #pragma unroll
            for (int j = 0; j < 32; ++j) a[j] = Lkk[lane * 33 + j];
            #pragma unroll
            for (int j = 0; j < 32; ++j) {
                float dj = __shfl_sync(0xffffffffu, a[j], j);
                float sj = sqrtf(dj);
                float lrj = (lane == j) ? sj : a[j] / sj;
                a[j] = lrj;
                #pragma unroll
                for (int c = j + 1; c < 32; ++c) {
                    float lcj = __shfl_sync(0xffffffffu, lrj, c);
                    a[c] -= lrj * lcj;
                }
            }
            #pragma unroll
            for (int j = 0; j < 32; ++j)
                if (j <= lane) Lkk[lane * 33 + j] = a[j];
            rinv[lane] = 1.f / a[lane];
            float ld = logf(a[lane]);
            #pragma unroll
            for (int o = 16; o; o >>= 1) ld += __shfl_xor_sync(0xffffffffu, ld, o);
            if (lane == 0) scal[6] += ld;
        }
        __syncthreads();

        if (tid < 32) {
            if (rank == 0) {
                float* wr = cov + (size_t)(k0 + tid) * LDA + k0;
                for (int j = 0; j <= tid; ++j) wr[j] = Lkk[tid * 33 + j];
            }
        } else if (pv1) {
            trsm_row(a1, Lkk, rinv);
            float* wr = cov + (size_t)(k0 + 32 + r1) * LDA + k0;
            #pragma unroll
            for (int w = 0; w < 8; ++w)
                ((float4*)wr)[w] = make_float4(a1[4*w], a1[4*w+1], a1[4*w+2], a1[4*w+3]);
            store_row_bf16(gH, gL, k0 + 32 + r1, 0, a1);
        }
        {   // leftover rows (kb==0 only)
            int rb = h1s + 480 + (tid - 32);
            if (tid >= 32 && tid < 48 && rb < h1e) {
                const float* rr = cov + (size_t)(k0 + 32 + rb) * LDA + k0;
                #pragma unroll
                for (int w = 0; w < 8; ++w) {
                    float4 q = ((const float4*)rr)[w];
                    a1[4*w] = q.x; a1[4*w+1] = q.y; a1[4*w+2] = q.z; a1[4*w+3] = q.w;
                }
                trsm_row(a1, Lkk, rinv);
                float* wr = cov + (size_t)(k0 + 32 + rb) * LDA + k0;
                #pragma unroll
                for (int w = 0; w < 8; ++w)
                    ((float4*)wr)[w] = make_float4(a1[4*w], a1[4*w+1], a1[4*w+2], a1[4*w+3]);
                store_row_bf16(gH, gL, k0 + 32 + rb, 0, a1);
            }
        }
        cluster_sync_();   // A: all panel1 rows solved + visible

        // ===== stage 2: diag2 + narrow update + panel2 (cols k0+32..63) =====
        for (int idx = tid; idx < 1024; idx += NTH) {
            int r = idx >> 5, c = idx & 31;
            Bb[r * 33 + c] = cov[(size_t)(k0 + 32 + r) * LDA + k0 + c];
        }
        const int h2len = (nt + 1) >> 1;
        const int h2s = rank * h2len;
        const int h2e = (rank == 0) ? h2len : nt;
        float A32[32], w2[32];
        const int r2 = h2s + tid - 32;
        const bool pv2 = (tid >= 32) && (r2 < h2e) && (nt > 0);
        if (pv2) {
            const float* rr = cov + (size_t)(k0 + 64 + r2) * LDA + k0;
            #pragma unroll
            for (int w = 0; w < 8; ++w) {
                float4 qa = ((const float4*)rr)[w];
                float4 qb = ((const float4*)(rr + 32))[w];
                A32[4*w] = qa.x; A32[4*w+1] = qa.y; A32[4*w+2] = qa.z; A32[4*w+3] = qa.w;
                w2[4*w]  = qb.x; w2[4*w+1]  = qb.y; w2[4*w+2]  = qb.z; w2[4*w+3]  = qb.w;
            }
        }
        __syncthreads();   // Bb ready

        for (int idx = tid; idx < 1024; idx += NTH) {   // diag2 adjust
            int r = idx >> 5, c = idx & 31;
            float v = 0.f;
            if (c <= r) {
                v = cov[(size_t)(k0 + 32 + r) * LDA + k0 + 32 + c];
                #pragma unroll
                for (int p = 0; p < 32; ++p)
                    v -= Bb[r * 33 + p] * Bb[c * 33 + p];
            }
            Lkk[r * 33 + c] = v;
        }
        __syncthreads();

        if (tid < 32) {     // factor diag2
            float a[32];
            #pragma unroll
            for (int j = 0; j < 32; ++j) a[j] = Lkk[lane * 33 + j];
            #pragma unroll
            for (int j = 0; j < 32; ++j) {
                float dj = __shfl_sync(0xffffffffu, a[j], j);
                float sj = sqrtf(dj);
                float lrj = (lane == j) ? sj : a[j] / sj;
                a[j] = lrj;
                #pragma unroll
                for (int c = j + 1; c < 32; ++c) {
                    float lcj = __shfl_sync(0xffffffffu, lrj, c);
                    a[c] -= lrj * lcj;
                }
            }
            #pragma unroll
            for (int j = 0; j < 32; ++j)
                if (j <= lane) Lkk[lane * 33 + j] = a[j];
            rinv[lane] = 1.f / a[lane];
            float ld = logf(a[lane]);
            #pragma unroll
            for (int o = 16; o; o >>= 1) ld += __shfl_xor_sync(0xffffffffu, ld, o);
            if (lane == 0) scal[6] += ld;
            if (rank == 0) {
                float* wr = cov + (size_t)(k0 + 32 + lane) * LDA + k0 + 32;
                for (int j = 0; j <= lane; ++j) wr[j] = Lkk[lane * 33 + j];
            }
        } else if (pv2) {
            // narrow update: w2 -= A32 * Bb^T
            #pragma unroll
            for (int c = 0; c < 32; ++c) {
                float s = w2[c];
                #pragma unroll
                for (int p = 0; p < 32; ++p)
                    s -= A32[p] * Bb[c * 33 + p];
                w2[c] = s;
            }
        }
        __syncthreads();

        if (pv2) {
            trsm_row(w2, Lkk, rinv);
            float* wr = cov + (size_t)(k0 + 64 + r2) * LDA + k0 + 32;
            #pragma unroll
            for (int w = 0; w < 8; ++w)
                ((float4*)wr)[w] = make_float4(w2[4*w], w2[4*w+1], w2[4*w+2], w2[4*w+3]);
            store_row_bf16(gH, gL, k0 + 64 + r2, 32, w2);
        }
        cluster_sync_();   // B: full K=64 panel in planes

        // ===== stage 3: trailing K=64 HMMA update from global planes =====
        if (nt > 0) {
            const int ntile = nt >> 5;
            const int npair = ntile * (ntile + 1) / 2;
            const int worker = rank * 16 + wid;
            const int g = lane >> 2, t = lane & 3;
            const int g0 = k0 + 64;

            for (int pair = worker; pair < npair; pair += 32) {
                // tib-major decode: counts per tib = tib+1
                int tib = 0, rem = pair;
                while (rem >= tib + 1) { rem -= tib + 1; ++tib; }
                const int tjb = rem;
                const int i0 = tib * 32, j0 = tjb * 32;
                const bool full = (tib != tjb);

                // C prefetch (full tiles)
                float2 cp[2][2][4];
                if (full) {
                    #pragma unroll
                    for (int mb = 0; mb < 2; ++mb)
                        #pragma unroll
                        for (int half = 0; half < 2; ++half) {
                            const float* rowp = cov + (size_t)(g0 + i0 + mb*16 + g + half*8) * LDA + g0 + j0;
                            #pragma unroll
                            for (int nb = 0; nb < 4; ++nb)
                                cp[mb][half][nb] = *(const float2*)(rowp + nb*8 + t*2);
                        }
                }

                float c[2][4][4];
                #pragma unroll
                for (int mb = 0; mb < 2; ++mb)
                    #pragma unroll
                    for (int nb = 0; nb < 4; ++nb)
                        #pragma unroll
                        for (int q = 0; q < 4; ++q) c[mb][nb][q] = 0.f;

                #pragma unroll
                for (int kc = 0; kc < 64; kc += 16) {
                    uint32_t aH[2][4], aL[2][4], bH[4][2], bL[4][2];
                    #pragma unroll
                    for (int mb = 0; mb < 2; ++mb) {
                        size_t r0 = (size_t)(g0 + i0 + mb*16 + g) * PP + kc + 2*t;
                        size_t r8 = r0 + 8 * PP;
                        aH[mb][0] = *(const uint32_t*)(gH + r0);
                        aH[mb][1] = *(const uint32_t*)(gH + r8);
                        aH[mb][2] = *(const uint32_t*)(gH + r0 + 8);
                        aH[mb][3] = *(const uint32_t*)(gH + r8 + 8);
                        aL[mb][0] = *(const uint32_t*)(gL + r0);
                        aL[mb][1] = *(const uint32_t*)(gL + r8);
                        aL[mb][2] = *(const uint32_t*)(gL + r0 + 8);
                        aL[mb][3] = *(const uint32_t*)(gL + r8 + 8);
                    }
                    #pragma unroll
                    for (int nb = 0; nb < 4; ++nb) {
                        size_t rj = (size_t)(g0 + j0 + nb*8 + g) * PP + kc + 2*t;
                        bH[nb][0] = *(const uint32_t*)(gH + rj);
                        bH[nb][1] = *(const uint32_t*)(gH + rj + 8);
                        bL[nb][0] = *(const uint32_t*)(gL + rj);
                        bL[nb][1] = *(const uint32_t*)(gL + rj + 8);
                    }
                    #pragma unroll
                    for (int mb = 0; mb < 2; ++mb)
                        #pragma unroll
                        for (int nb = 0; nb < 4; ++nb) {
                            hmma(c[mb][nb], aH[mb], bH[nb]);
                            hmma(c[mb][nb], aH[mb], bL[nb]);
                            hmma(c[mb][nb], aL[mb], bH[nb]);
                        }
                }

                if (full) {
                    #pragma unroll
                    for (int mb = 0; mb < 2; ++mb)
                        #pragma unroll
                        for (int half = 0; half < 2; ++half) {
                            float* rowp = cov + (size_t)(g0 + i0 + mb*16 + g + half*8) * LDA + g0 + j0;
                            #pragma unroll
                            for (int nb = 0; nb < 4; ++nb) {
                                float2 v = cp[mb][half][nb];
                                v.x -= c[mb][nb][half*2];
                                v.y -= c[mb][nb][half*2 + 1];
                                *(float2*)(rowp + nb*8 + t*2) = v;
                            }
                        }
                } else {
                    #pragma unroll
                    for (int mb = 0; mb < 2; ++mb)
                        #pragma unroll
                        for (int half = 0; half < 2; ++half) {
                            int i_loc = i0 + mb*16 + g + half*8;
                            float* row = cov + (size_t)(g0 + i_loc) * LDA + g0;
                            #pragma unroll
                            for (int nb = 0; nb < 4; ++nb) {
                                int j = j0 + nb*8 + t*2;
                                float cx = c[mb][nb][half*2];
                                float cy = c[mb][nb][half*2 + 1];
                                if (j + 1 <= i_loc) {
                                    float2 v = *(float2*)(row + j);
                                    v.x -= cx; v.y -= cy;
                                    *(float2*)(row + j) = v;
                                } else if (j <= i_loc) {
                                    row[j] -= cx;
                                }
                            }
                        }
                }
            }
        }
        cluster_sync_();   // C: trailing fully updated
    }

    // ---- forward substitution + output: rank 0 only ----
    if (rank != 0) return;

    float* rhs = xs;
    for (int i = tid; i < NN; i += NTH) rhs[i] = y[i] - beta;
    __syncthreads();

    for (int kb = 0; kb < 32; ++kb) {
        const int k0 = kb * 32;
        if (tid < 32) {
            const float* lrow = cov + (size_t)(k0 + lane) * LDA + k0;
            float lr[32];
            #pragma unroll
            for (int w = 0; w < 8; ++w) {
                float4 q = ((const float4*)lrow)[w];
                lr[4*w] = q.x; lr[4*w+1] = q.y; lr[4*w+2] = q.z; lr[4*w+3] = q.w;
            }
            float t = rhs[k0 + lane];
            #pragma unroll
            for (int j = 0; j < 32; ++j) {
                if (lane == j) t /= lr[j];
                float sj = __shfl_sync(0xffffffffu, t, j);
                if (lane > j) t -= sj * lr[j];
            }
            rhs[k0 + lane] = t;
        }
        __syncthreads();
        for (int i = k0 + 32 + tid; i < NN; i += NTH) {
            const float* row = cov + (size_t)i * LDA + k0;
            float acc = 0.f;
            #pragma unroll
            for (int w = 0; w < 8; ++w) {
                float4 c4 = ((const float4*)row)[w];
                acc += c4.x * rhs[k0 + 4*w]     + c4.y * rhs[k0 + 4*w + 1]
                     + c4.z * rhs[k0 + 4*w + 2] + c4.w * rhs[k0 + 4*w + 3];
            }
            rhs[i] -= acc;
        }
        __syncthreads();
    }

    float q = 0.f;
    for (int i = tid; i < NN; i += NTH) { float v = rhs[i]; q += v * v; }
    red[tid] = q;
    __syncthreads();
    for (int s = NTH / 2; s; s >>= 1) {
        if (tid < s) red[tid] += red[tid + s];
        __syncthreads();
    }
    if (tid == 0) {
        float logdet = 2.f * scal[6];
        const float LN2PI = 1.8378770664093453f;
        out[m] = -0.5f * (red[0] + logdet + 1024.f * LN2PI) + scal[5];
    }
}

extern "C" void kernel_launch(void* const* d_in, const int* in_sizes, int n_in,
                              void* d_out, int out_size)
{
    (void)in_sizes; (void)n_in; (void)out_size;
    vi_kernel<<<2 * MM, NTH>>>(
        (const float*)d_in[0], (const float*)d_in[1], (const float*)d_in[2],
        (const float*)d_in[3], (const float*)d_in[4],
        (const float*)d_in[5], (const float*)d_in[6],
        (const float*)d_in[7], (const float*)d_in[8],
        (const float*)d_in[9], (const float*)d_in[10],
        (const float*)d_in[11], (const float*)d_in[12],
        (float*)d_out);
}

// round 11
// speedup vs baseline: 1.1429x; 1.1429x over previous
#include <cuda_runtime.h>
#include <cuda_bf16.h>
#include <math.h>
#include <stdint.h>

#define NN 1024
#define MM 64
#define LDA 1040
#define PP 64               // pitch of bf16 panel planes (both 32-col halves)

__device__ float    g_cov[(size_t)MM * NN * LDA];
__device__ uint16_t g_pH[(size_t)MM * NN * PP];
__device__ uint16_t g_pL[(size_t)MM * NN * PP];
__device__ float    g_ld[(size_t)MM * 32 * 1056];   // factored 32x32 diag blocks (33-pitch)
__device__ float    g_scal[MM * 8];
__device__ float    g_ldet[MM * 32];

__device__ __forceinline__ void hmma(float* c, const uint32_t* a, const uint32_t* b) {
    asm volatile("mma.sync.aligned.m16n8k16.row.col.f32.bf16.bf16.f32 "
        "{%0,%1,%2,%3},{%4,%5,%6,%7},{%8,%9},{%0,%1,%2,%3};"
        : "+f"(c[0]), "+f"(c[1]), "+f"(c[2]), "+f"(c[3])
        : "r"(a[0]), "r"(a[1]), "r"(a[2]), "r"(a[3]), "r"(b[0]), "r"(b[1]));
}
__device__ __forceinline__ float sp_(float x) {
    return fmaxf(x, 0.f) + log1pf(expf(-fabsf(x))) + 1e-7f;
}
__device__ __forceinline__ float log_normal_(float v, float mean, float s, float eps) {
    const float C = -0.91893853320467274178f;
    float d = v - mean;
    return -d * d / (2.f * s * s + eps) - logf(s) + C;
}
__device__ __forceinline__ float log_lognormal_(float v, float mean, float s, float eps) {
    const float C = -0.91893853320467274178f;
    float lv = logf(v);
    float d = lv - mean;
    return -d * d / (2.f * s * s + eps) - lv - logf(s) + C;
}
__device__ __forceinline__ void trsm_row(float* a, const float* Lkk, const float* rinv) {
    #pragma unroll
    for (int j = 0; j < 32; ++j) {
        float s = a[j];
        #pragma unroll
        for (int p = 0; p < j; ++p) s -= a[p] * Lkk[j * 33 + p];
        a[j] = s * rinv[j];
    }
}
__device__ __forceinline__ void store_row_bf16(uint16_t* H, uint16_t* L, int row, int cb, const float* a) {
    uint32_t hw[16], lw[16];
    #pragma unroll
    for (int q = 0; q < 16; ++q) {
        float f0 = a[2*q], f1 = a[2*q+1];
        __nv_bfloat16 h0 = __float2bfloat16(f0);
        __nv_bfloat16 h1 = __float2bfloat16(f1);
        __nv_bfloat16 l0 = __float2bfloat16(f0 - __bfloat162float(h0));
        __nv_bfloat16 l1 = __float2bfloat16(f1 - __bfloat162float(h1));
        hw[q] = (uint32_t)__bfloat16_as_ushort(h0) | ((uint32_t)__bfloat16_as_ushort(h1) << 16);
        lw[q] = (uint32_t)__bfloat16_as_ushort(l0) | ((uint32_t)__bfloat16_as_ushort(l1) << 16);
    }
    uint32_t* hr = (uint32_t*)(H + (size_t)row * PP + cb);
    uint32_t* lr = (uint32_t*)(L + (size_t)row * PP + cb);
    #pragma unroll
    for (int q = 0; q < 4; ++q) {
        ((uint4*)hr)[q] = make_uint4(hw[4*q], hw[4*q+1], hw[4*q+2], hw[4*q+3]);
        ((uint4*)lr)[q] = make_uint4(lw[4*q], lw[4*q+1], lw[4*q+2], lw[4*q+3]);
    }
}

// warp-0 32x32 Cholesky of smem Lkk (33-pitch); writes rinv; returns logdet partial on lane0
__device__ __forceinline__ float diag_factor(float* Lkk, float* rinv, int lane) {
    float a[32];
    #pragma unroll
    for (int j = 0; j < 32; ++j) a[j] = Lkk[lane * 33 + j];
    #pragma unroll
    for (int j = 0; j < 32; ++j) {
        float dj = __shfl_sync(0xffffffffu, a[j], j);
        float sj = sqrtf(dj);
        float lrj = (lane == j) ? sj : a[j] / sj;
        a[j] = lrj;
        #pragma unroll
        for (int c = j + 1; c < 32; ++c) {
            float lcj = __shfl_sync(0xffffffffu, lrj, c);
            a[c] -= lrj * lcj;
        }
    }
    #pragma unroll
    for (int j = 0; j < 32; ++j)
        if (j <= lane) Lkk[lane * 33 + j] = a[j];
    rinv[lane] = 1.f / a[lane];
    float ld = logf(a[lane]);
    #pragma unroll
    for (int o = 16; o; o >>= 1) ld += __shfl_xor_sync(0xffffffffu, ld, o);
    return ld;
}

// ---------------- kernel: scalars ----------------
extern "C" __global__ void k_scal(const float* __restrict__ z,
    const float* qbm, const float* qbs, const float* qsm, const float* qss,
    const float* qem, const float* qes, const float* qzm, const float* qzs,
    const float* qnm, const float* qns)
{
    int m = blockIdx.x;
    if (threadIdx.x != 0) return;
    float s0 = sp_(sqrtf(logf(2.f)));
    float z0 = z[m*5+0], z1 = z[m*5+1], z2 = z[m*5+2], z3 = z[m*5+3], z4 = z[m*5+4];
    float sps = sp_(*qss), spb = sp_(*qbs), spe = sp_(*qes), spz = sp_(*qzs), spn = sp_(*qns);
    float sigma2 = expf(z0 * sps + *qsm);
    float beta   = z1 * spb + *qbm;
    float eta    = expf(z2 * spe + *qem);
    float lsZ    = expf(z3 * spz + *qzm);
    float lsN    = expf(z4 * spn + *qnm);
    float lp = log_normal_(beta, 0.f, 1.f, 1e-5f)
             + log_lognormal_(sigma2, 1.f, s0, 1e-6f)
             + log_lognormal_(eta,    1.f, s0, 1e-6f)
             + log_lognormal_(lsZ,    1.f, s0, 1e-6f)
             + log_lognormal_(lsN,    1.f, s0, 1e-6f);
    float lq = log_normal_(beta, *qbm, spb, 1e-5f)
             + log_lognormal_(sigma2, *qsm, sps, 1e-6f)
             + log_lognormal_(eta,    *qem, spe, 1e-6f)
             + log_lognormal_(lsZ,    *qzm, spz, 1e-6f)
             + log_lognormal_(lsN,    *qnm, spn, 1e-6f);
    g_scal[m*8+0] = beta; g_scal[m*8+1] = sigma2; g_scal[m*8+2] = eta;
    g_scal[m*8+3] = lsZ;  g_scal[m*8+4] = lsN;    g_scal[m*8+5] = lp - lq;
}

// ---------------- kernel: cov build (grid: (2, MM)) ----------------
extern "C" __global__ void __launch_bounds__(512, 1)
k_build(const float* __restrict__ x)
{
    __shared__ float xs[2048];
    const int m = blockIdx.y, par = blockIdx.x, tid = threadIdx.x;
    float* cov = g_cov + (size_t)m * NN * LDA;
    const float eta = g_scal[m*8+2], sigma2 = g_scal[m*8+1];
    const float lsZ = g_scal[m*8+3], lsN = g_scal[m*8+4];
    for (int i = tid; i < NN; i += 512) {
        xs[i]      = x[2*i]   / lsZ;
        xs[NN + i] = x[2*i+1] / lsN;
    }
    __syncthreads();
    const float* xs0 = xs;
    const float* xs1 = xs + NN;
    int i = par + 2 * tid;
    float xi0 = xs0[i], xi1 = xs1[i];
    float* row = cov + (size_t)i * LDA;
    int j4 = i & ~3;
    for (int j = 0; j < j4; j += 4) {
        float4 a0 = *(const float4*)(xs0 + j);
        float4 a1 = *(const float4*)(xs1 + j);
        float4 o; float d0, d1;
        d0 = xi0 - a0.x; d1 = xi1 - a1.x; o.x = eta * __expf(-0.5f * (d0*d0 + d1*d1));
        d0 = xi0 - a0.y; d1 = xi1 - a1.y; o.y = eta * __expf(-0.5f * (d0*d0 + d1*d1));
        d0 = xi0 - a0.z; d1 = xi1 - a1.z; o.z = eta * __expf(-0.5f * (d0*d0 + d1*d1));
        d0 = xi0 - a0.w; d1 = xi1 - a1.w; o.w = eta * __expf(-0.5f * (d0*d0 + d1*d1));
        *(float4*)(row + j) = o;
    }
    for (int j = j4; j < i; ++j) {
        float d0 = xi0 - xs0[j], d1 = xi1 - xs1[j];
        row[j] = eta * __expf(-0.5f * (d0*d0 + d1*d1));
    }
    row[i] = eta + sigma2;
}

// ---------------- kernel: panel stage 1 (grid: (P1, MM)) ----------------
extern "C" __global__ void __launch_bounds__(512, 1)
k_panel1(int kb)
{
    __shared__ float Lkk[1056];
    __shared__ float rinv[32];
    const int m = blockIdx.y, pid = blockIdx.x, tid = threadIdx.x, lane = tid & 31;
    const int k0 = kb * 64;
    const int R1 = NN - k0 - 32;
    float* cov = g_cov + (size_t)m * NN * LDA;
    uint16_t* gH = g_pH + (size_t)m * NN * PP;
    uint16_t* gL = g_pL + (size_t)m * NN * PP;

    for (int idx = tid; idx < 1024; idx += 512) {
        int r = idx >> 5, c = idx & 31;
        Lkk[r * 33 + c] = (c <= r) ? cov[(size_t)(k0 + r) * LDA + k0 + c] : 0.f;
    }
    float a1[32];
    const int r1 = pid * 512 + tid;
    const bool pv = r1 < R1;
    if (pv) {
        const float* rr = cov + (size_t)(k0 + 32 + r1) * LDA + k0;
        #pragma unroll
        for (int w = 0; w < 8; ++w) {
            float4 q = ((const float4*)rr)[w];
            a1[4*w] = q.x; a1[4*w+1] = q.y; a1[4*w+2] = q.z; a1[4*w+3] = q.w;
        }
    }
    __syncthreads();
    if (tid < 32) {
        float ld = diag_factor(Lkk, rinv, lane);
        if (pid == 0 && lane == 0) g_ldet[m * 32 + 2 * kb] = ld;
    }
    __syncthreads();
    if (pid == 0)
        for (int idx = tid; idx < 1056; idx += 512)
            g_ld[((size_t)m * 32 + 2 * kb) * 1056 + idx] = Lkk[idx];
    if (pv) {
        trsm_row(a1, Lkk, rinv);
        float* wr = cov + (size_t)(k0 + 32 + r1) * LDA + k0;
        #pragma unroll
        for (int w = 0; w < 8; ++w)
            ((float4*)wr)[w] = make_float4(a1[4*w], a1[4*w+1], a1[4*w+2], a1[4*w+3]);
        store_row_bf16(gH, gL, k0 + 32 + r1, 0, a1);
    }
}

// ---------------- kernel: panel stage 2 (grid: (P2, MM)) ----------------
extern "C" __global__ void __launch_bounds__(512, 1)
k_panel2(int kb)
{
    __shared__ float Lkk[1056];
    __shared__ float Bb[1056];
    __shared__ float rinv[32];
    const int m = blockIdx.y, pid = blockIdx.x, tid = threadIdx.x, lane = tid & 31;
    const int k0 = kb * 64;
    const int nt = NN - k0 - 64;
    float* cov = g_cov + (size_t)m * NN * LDA;
    uint16_t* gH = g_pH + (size_t)m * NN * PP;
    uint16_t* gL = g_pL + (size_t)m * NN * PP;

    // Bb = solved rows k0+32..63, cols k0..31 (written by k_panel1 this step)
    for (int idx = tid; idx < 1024; idx += 512) {
        int r = idx >> 5, c = idx & 31;
        Bb[r * 33 + c] = cov[(size_t)(k0 + 32 + r) * LDA + k0 + c];
    }
    float A32[32], w2[32];
    const int r2 = pid * 512 + tid;
    const bool pv = (r2 < nt);
    if (pv) {
        const float* rr = cov + (size_t)(k0 + 64 + r2) * LDA + k0;
        #pragma unroll
        for (int w = 0; w < 8; ++w) {
            float4 qa = ((const float4*)rr)[w];
            float4 qb = ((const float4*)(rr + 32))[w];
            A32[4*w] = qa.x; A32[4*w+1] = qa.y; A32[4*w+2] = qa.z; A32[4*w+3] = qa.w;
            w2[4*w]  = qb.x; w2[4*w+1]  = qb.y; w2[4*w+2]  = qb.z; w2[4*w+3]  = qb.w;
        }
    }
    __syncthreads();
    // diag2 adjust: Lkk = raw diag2 - Bb*Bb^T (lower)
    for (int idx = tid; idx < 1024; idx += 512) {
        int r = idx >> 5, c = idx & 31;
        float v = 0.f;
        if (c <= r) {
            v = cov[(size_t)(k0 + 32 + r) * LDA + k0 + 32 + c];
            #pragma unroll
            for (int p = 0; p < 32; ++p)
                v -= Bb[r * 33 + p] * Bb[c * 33 + p];
        }
        Lkk[r * 33 + c] = v;
    }
    // narrow update (independent of diag2 factor)
    if (pv) {
        #pragma unroll
        for (int c = 0; c < 32; ++c) {
            float s = w2[c];
            #pragma unroll
            for (int p = 0; p < 32; ++p)
                s -= A32[p] * Bb[c * 33 + p];
            w2[c] = s;
        }
    }
    __syncthreads();
    if (tid < 32) {
        float ld = diag_factor(Lkk, rinv, lane);
        if (pid == 0 && lane == 0) g_ldet[m * 32 + 2 * kb + 1] = ld;
    }
    __syncthreads();
    if (pid == 0)
        for (int idx = tid; idx < 1056; idx += 512)
            g_ld[((size_t)m * 32 + 2 * kb + 1) * 1056 + idx] = Lkk[idx];
    if (pv) {
        trsm_row(w2, Lkk, rinv);
        float* wr = cov + (size_t)(k0 + 64 + r2) * LDA + k0 + 32;
        #pragma unroll
        for (int w = 0; w < 8; ++w)
            ((float4*)wr)[w] = make_float4(w2[4*w], w2[4*w+1], w2[4*w+2], w2[4*w+3]);
        store_row_bf16(gH, gL, k0 + 64 + r2, 32, w2);
    }
}

// ---------------- kernel: trailing K=64 HMMA update (grid: (nblk, MM), 256 thr) ----------------
extern "C" __global__ void __launch_bounds__(256, 2)
k_trail(int kb)
{
    const int m = blockIdx.y, tid = threadIdx.x;
    const int wid = tid >> 5, lane = tid & 31;
    const int k0 = kb * 64;
    const int nt = NN - k0 - 64;
    const int ntile = nt >> 5;
    const int npair = ntile * (ntile + 1) / 2;
    const int pair = blockIdx.x * 8 + wid;
    if (pair >= npair) return;

    float* cov = g_cov + (size_t)m * NN * LDA;
    const uint16_t* gH = g_pH + (size_t)m * NN * PP;
    const uint16_t* gL = g_pL + (size_t)m * NN * PP;
    const int g = lane >> 2, t = lane & 3;
    const int g0 = k0 + 64;

    int tib = 0, rem = pair;
    while (rem >= tib + 1) { rem -= tib + 1; ++tib; }
    const int tjb = rem;
    const int i0 = tib * 32, j0 = tjb * 32;
    const bool full = (tib != tjb);

    float2 cp[2][2][4];
    if (full) {
        #pragma unroll
        for (int mb = 0; mb < 2; ++mb)
            #pragma unroll
            for (int half = 0; half < 2; ++half) {
                const float* rowp = cov + (size_t)(g0 + i0 + mb*16 + g + half*8) * LDA + g0 + j0;
                #pragma unroll
                for (int nb = 0; nb < 4; ++nb)
                    cp[mb][half][nb] = *(const float2*)(rowp + nb*8 + t*2);
            }
    }

    float c[2][4][4];
    #pragma unroll
    for (int mb = 0; mb < 2; ++mb)
        #pragma unroll
        for (int nb = 0; nb < 4; ++nb)
            #pragma unroll
            for (int q = 0; q < 4; ++q) c[mb][nb][q] = 0.f;

    #pragma unroll
    for (int kc = 0; kc < 64; kc += 16) {
        uint32_t aH[2][4], aL[2][4], bH[4][2], bL[4][2];
        #pragma unroll
        for (int mb = 0; mb < 2; ++mb) {
            size_t r0 = (size_t)(g0 + i0 + mb*16 + g) * PP + kc + 2*t;
            size_t r8 = r0 + 8 * PP;
            aH[mb][0] = *(const uint32_t*)(gH + r0);
            aH[mb][1] = *(const uint32_t*)(gH + r8);
            aH[mb][2] = *(const uint32_t*)(gH + r0 + 8);
            aH[mb][3] = *(const uint32_t*)(gH + r8 + 8);
            aL[mb][0] = *(const uint32_t*)(gL + r0);
            aL[mb][1] = *(const uint32_t*)(gL + r8);
            aL[mb][2] = *(const uint32_t*)(gL + r0 + 8);
            aL[mb][3] = *(const uint32_t*)(gL + r8 + 8);
        }
        #pragma unroll
        for (int nb = 0; nb < 4; ++nb) {
            size_t rj = (size_t)(g0 + j0 + nb*8 + g) * PP + kc + 2*t;
            bH[nb][0] = *(const uint32_t*)(gH + rj);
            bH[nb][1] = *(const uint32_t*)(gH + rj + 8);
            bL[nb][0] = *(const uint32_t*)(gL + rj);
            bL[nb][1] = *(const uint32_t*)(gL + rj + 8);
        }
        #pragma unroll
        for (int mb = 0; mb < 2; ++mb)
            #pragma unroll
            for (int nb = 0; nb < 4; ++nb) {
                hmma(c[mb][nb], aH[mb], bH[nb]);
                hmma(c[mb][nb], aH[mb], bL[nb]);
                hmma(c[mb][nb], aL[mb], bH[nb]);
            }
    }

    if (full) {
        #pragma unroll
        for (int mb = 0; mb < 2; ++mb)
            #pragma unroll
            for (int half = 0; half < 2; ++half) {
                float* rowp = cov + (size_t)(g0 + i0 + mb*16 + g + half*8) * LDA + g0 + j0;
                #pragma unroll
                for (int nb = 0; nb < 4; ++nb) {
                    float2 v = cp[mb][half][nb];
                    v.x -= c[mb][nb][half*2];
                    v.y -= c[mb][nb][half*2 + 1];
                    *(float2*)(rowp + nb*8 + t*2) = v;
                }
            }
    } else {
        #pragma unroll
        for (int mb = 0; mb < 2; ++mb)
            #pragma unroll
            for (int half = 0; half < 2; ++half) {
                int i_loc = i0 + mb*16 + g + half*8;
                float* row = cov + (size_t)(g0 + i_loc) * LDA + g0;
                #pragma unroll
                for (int nb = 0; nb < 4; ++nb) {
                    int j = j0 + nb*8 + t*2;
                    float cx = c[mb][nb][half*2];
                    float cy = c[mb][nb][half*2 + 1];
                    if (j + 1 <= i_loc) {
                        float2 v = *(float2*)(row + j);
                        v.x -= cx; v.y -= cy;
                        *(float2*)(row + j) = v;
                    } else if (j <= i_loc) {
                        row[j] -= cx;
                    }
                }
            }
    }
}

// ---------------- kernel: forward substitution + output (grid: MM) ----------------
extern "C" __global__ void __launch_bounds__(512, 1)
k_finish(const float* __restrict__ y, float* __restrict__ out)
{
    __shared__ float rhs[NN];
    __shared__ float red[512];
    const int m = blockIdx.x, tid = threadIdx.x, lane = tid & 31;
    float* cov = g_cov + (size_t)m * NN * LDA;
    const float beta = g_scal[m*8+0];

    for (int i = tid; i < NN; i += 512) rhs[i] = y[i] - beta;
    __syncthreads();

    for (int kb2 = 0; kb2 < 32; ++kb2) {
        const int k0 = kb2 * 32;
        if (tid < 32) {
            const float* lrow = g_ld + ((size_t)m * 32 + kb2) * 1056 + lane * 33;
            float lr[32];
            #pragma unroll
            for (int j = 0; j < 32; ++j) lr[j] = lrow[j];
            float t = rhs[k0 + lane];
            #pragma unroll
            for (int j = 0; j < 32; ++j) {
                if (lane == j) t /= lr[j];
                float sj = __shfl_sync(0xffffffffu, t, j);
                if (lane > j) t -= sj * lr[j];
            }
            rhs[k0 + lane] = t;
        }
        __syncthreads();
        for (int i = k0 + 32 + tid; i < NN; i += 512) {
            const float* row = cov + (size_t)i * LDA + k0;
            float acc = 0.f;
            #pragma unroll
            for (int w = 0; w < 8; ++w) {
                float4 c4 = ((const float4*)row)[w];
                acc += c4.x * rhs[k0 + 4*w]     + c4.y * rhs[k0 + 4*w + 1]
                     + c4.z * rhs[k0 + 4*w + 2] + c4.w * rhs[k0 + 4*w + 3];
            }
            rhs[i] -= acc;
        }
        __syncthreads();
    }

    float q = 0.f;
    for (int i = tid; i < NN; i += 512) { float v = rhs[i]; q += v * v; }
    red[tid] = q;
    __syncthreads();
    for (int s = 256; s; s >>= 1) {
        if (tid < s) red[tid] += red[tid + s];
        __syncthreads();
    }
    if (tid == 0) {
        float ldsum = 0.f;
        for (int d = 0; d < 32; ++d) ldsum += g_ldet[m * 32 + d];
        const float LN2PI = 1.8378770664093453f;
        out[m] = -0.5f * (red[0] + 2.f * ldsum + 1024.f * LN2PI) + g_scal[m*8+5];
    }
}

extern "C" void kernel_launch(void* const* d_in, const int* in_sizes, int n_in,
                              void* d_out, int out_size)
{
    (void)in_sizes; (void)n_in; (void)out_size;
    const float* x = (const float*)d_in[0];
    const float* y = (const float*)d_in[1];
    const float* z = (const float*)d_in[2];

    k_scal<<<MM, 32>>>(z,
        (const float*)d_in[3], (const float*)d_in[4],
        (const float*)d_in[5], (const float*)d_in[6],
        (const float*)d_in[7], (const float*)d_in[8],
        (const float*)d_in[9], (const float*)d_in[10],
        (const float*)d_in[11], (const float*)d_in[12]);
    k_build<<<dim3(2, MM), 512>>>(x);

    for (int kb = 0; kb < 16; ++kb) {
        int R1 = NN - kb * 64 - 32;
        int P1 = (R1 + 511) / 512;
        k_panel1<<<dim3(P1, MM), 512>>>(kb);

        int nt = NN - kb * 64 - 64;
        int P2 = nt > 0 ? (nt + 511) / 512 : 1;
        k_panel2<<<dim3(P2, MM), 512>>>(kb);

        if (nt > 0) {
            int ntile = nt / 32;
            int npair = ntile * (ntile + 1) / 2;
            int nblk = (npair + 7) / 8;
            k_trail<<<dim3(nblk, MM), 256>>>(kb);
        }
    }
    k_finish<<<MM, 512>>>(y, (float*)d_out);
}

// round 13
// speedup vs baseline: 1.1518x; 1.0078x over previous
#include <cuda_runtime.h>
#include <cuda_bf16.h>
#include <math.h>
#include <stdint.h>

#define NN 1024
#define MM 64
#define LDA 1040
#define PP 64               // pitch of bf16 panel planes

__device__ float    g_cov[(size_t)MM * NN * LDA];
__device__ uint16_t g_pH[(size_t)MM * NN * PP];
__device__ uint16_t g_pL[(size_t)MM * NN * PP];
__device__ float    g_ld[(size_t)MM * 32 * 1056];    // factored diag blocks (33-pitch, lower)
__device__ uint16_t g_iH[(size_t)MM * 32 * 1024];    // inv(L) bf16 hi, 32x32 row-major
__device__ uint16_t g_iL[(size_t)MM * 32 * 1024];    // inv(L) bf16 lo
__device__ float    g_scal[MM * 8];
__device__ float    g_ldet[MM * 32];

__device__ __forceinline__ void hmma(float* c, const uint32_t* a, const uint32_t* b) {
    asm volatile("mma.sync.aligned.m16n8k16.row.col.f32.bf16.bf16.f32 "
        "{%0,%1,%2,%3},{%4,%5,%6,%7},{%8,%9},{%0,%1,%2,%3};"
        : "+f"(c[0]), "+f"(c[1]), "+f"(c[2]), "+f"(c[3])
        : "r"(a[0]), "r"(a[1]), "r"(a[2]), "r"(a[3]), "r"(b[0]), "r"(b[1]));
}
__device__ __forceinline__ void cvt2(float xx, float yy, uint32_t& h, uint32_t& l) {
    __nv_bfloat16 h0 = __float2bfloat16(xx), h1 = __float2bfloat16(yy);
    __nv_bfloat16 l0 = __float2bfloat16(xx - __bfloat162float(h0));
    __nv_bfloat16 l1 = __float2bfloat16(yy - __bfloat162float(h1));
    h = (uint32_t)__bfloat16_as_ushort(h0) | ((uint32_t)__bfloat16_as_ushort(h1) << 16);
    l = (uint32_t)__bfloat16_as_ushort(l0) | ((uint32_t)__bfloat16_as_ushort(l1) << 16);
}
__device__ __forceinline__ float sp_(float x) {
    return fmaxf(x, 0.f) + log1pf(expf(-fabsf(x))) + 1e-7f;
}
__device__ __forceinline__ float log_normal_(float v, float mean, float s, float eps) {
    const float C = -0.91893853320467274178f;
    float d = v - mean;
    return -d * d / (2.f * s * s + eps) - logf(s) + C;
}
__device__ __forceinline__ float log_lognormal_(float v, float mean, float s, float eps) {
    const float C = -0.91893853320467274178f;
    float lv = logf(v);
    float d = lv - mean;
    return -d * d / (2.f * s * s + eps) - lv - logf(s) + C;
}

// factor a[32] (lane = row; a[j]=0 for j>lane on entry), store to smem Lf/rinvs and global gld/ldet
__device__ __forceinline__ void factor_store(float* a, int lane, float* Lf, float* rinvs,
                                             float* gld, float* ldet_out)
{
    #pragma unroll
    for (int j = 0; j < 32; ++j) {
        float dj = __shfl_sync(0xffffffffu, a[j], j);
        float sj = sqrtf(dj);
        float lrj = (lane == j) ? sj : a[j] / sj;
        a[j] = lrj;
        #pragma unroll
        for (int cc = j + 1; cc < 32; ++cc)
            a[cc] -= lrj * __shfl_sync(0xffffffffu, lrj, cc);
    }
    #pragma unroll
    for (int j = 0; j < 32; ++j) {
        float v = (j <= lane) ? a[j] : 0.f;
        Lf[lane * 33 + j] = v;
        gld[lane * 33 + j] = v;
    }
    rinvs[lane] = 1.f / a[lane];
    float ld = logf(a[lane]);
    #pragma unroll
    for (int o = 16; o; o >>= 1) ld += __shfl_xor_sync(0xffffffffu, ld, o);
    if (lane == 0) *ldet_out = ld;
}

// lane j computes column j of inv(L) from smem Lf/rinvs; stores bf16 hi/lo planes
__device__ __forceinline__ void invert_store(int lane, const float* Lf, const float* rinvs,
                                             uint16_t* oH, uint16_t* oL)
{
    float xv[32];
    #pragma unroll
    for (int i = 0; i < 32; ++i) {
        float s = (i == lane) ? 1.f : 0.f;
        #pragma unroll
        for (int p = 0; p < 31; ++p)
            if (p < i) s -= Lf[i * 33 + p] * xv[p];
        xv[i] = s * rinvs[i];
    }
    #pragma unroll
    for (int i = 0; i < 32; ++i) {
        __nv_bfloat16 h = __float2bfloat16(xv[i]);
        __nv_bfloat16 l = __float2bfloat16(xv[i] - __bfloat162float(h));
        oH[i * 32 + lane] = __bfloat16_as_ushort(h);
        oL[i * 32 + lane] = __bfloat16_as_ushort(l);
    }
}

// ---------------- scalars ----------------
extern "C" __global__ void k_scal(const float* __restrict__ z,
    const float* qbm, const float* qbs, const float* qsm, const float* qss,
    const float* qem, const float* qes, const float* qzm, const float* qzs,
    const float* qnm, const float* qns)
{
    int m = blockIdx.x;
    if (threadIdx.x != 0) return;
    float s0 = sp_(sqrtf(logf(2.f)));
    float z0 = z[m*5+0], z1 = z[m*5+1], z2 = z[m*5+2], z3 = z[m*5+3], z4 = z[m*5+4];
    float sps = sp_(*qss), spb = sp_(*qbs), spe = sp_(*qes), spz = sp_(*qzs), spn = sp_(*qns);
    float sigma2 = expf(z0 * sps + *qsm);
    float beta   = z1 * spb + *qbm;
    float eta    = expf(z2 * spe + *qem);
    float lsZ    = expf(z3 * spz + *qzm);
    float lsN    = expf(z4 * spn + *qnm);
    float lp = log_normal_(beta, 0.f, 1.f, 1e-5f)
             + log_lognormal_(sigma2, 1.f, s0, 1e-6f)
             + log_lognormal_(eta,    1.f, s0, 1e-6f)
             + log_lognormal_(lsZ,    1.f, s0, 1e-6f)
             + log_lognormal_(lsN,    1.f, s0, 1e-6f);
    float lq = log_normal_(beta, *qbm, spb, 1e-5f)
             + log_lognormal_(sigma2, *qsm, sps, 1e-6f)
             + log_lognormal_(eta,    *qem, spe, 1e-6f)
             + log_lognormal_(lsZ,    *qzm, spz, 1e-6f)
             + log_lognormal_(lsN,    *qnm, spn, 1e-6f);
    g_scal[m*8+0] = beta; g_scal[m*8+1] = sigma2; g_scal[m*8+2] = eta;
    g_scal[m*8+3] = lsZ;  g_scal[m*8+4] = lsN;    g_scal[m*8+5] = lp - lq;
}

// ---------------- cov build (grid: (2, MM)) ----------------
extern "C" __global__ void __launch_bounds__(512, 1)
k_build(const float* __restrict__ x)
{
    __shared__ float xs[2048];
    const int m = blockIdx.y, par = blockIdx.x, tid = threadIdx.x;
    float* cov = g_cov + (size_t)m * NN * LDA;
    const float eta = g_scal[m*8+2], sigma2 = g_scal[m*8+1];
    const float lsZ = g_scal[m*8+3], lsN = g_scal[m*8+4];
    for (int i = tid; i < NN; i += 512) {
        xs[i]      = x[2*i]   / lsZ;
        xs[NN + i] = x[2*i+1] / lsN;
    }
    __syncthreads();
    const float* xs0 = xs;
    const float* xs1 = xs + NN;
    int i = par + 2 * tid;
    float xi0 = xs0[i], xi1 = xs1[i];
    float* row = cov + (size_t)i * LDA;
    int j4 = i & ~3;
    for (int j = 0; j < j4; j += 4) {
        float4 a0 = *(const float4*)(xs0 + j);
        float4 a1 = *(const float4*)(xs1 + j);
        float4 o; float d0, d1;
        d0 = xi0 - a0.x; d1 = xi1 - a1.x; o.x = eta * __expf(-0.5f * (d0*d0 + d1*d1));
        d0 = xi0 - a0.y; d1 = xi1 - a1.y; o.y = eta * __expf(-0.5f * (d0*d0 + d1*d1));
        d0 = xi0 - a0.z; d1 = xi1 - a1.z; o.z = eta * __expf(-0.5f * (d0*d0 + d1*d1));
        d0 = xi0 - a0.w; d1 = xi1 - a1.w; o.w = eta * __expf(-0.5f * (d0*d0 + d1*d1));
        *(float4*)(row + j) = o;
    }
    for (int j = j4; j < i; ++j) {
        float d0 = xi0 - xs0[j], d1 = xi1 - xs1[j];
        row[j] = eta * __expf(-0.5f * (d0*d0 + d1*d1));
    }
    row[i] = eta + sigma2;
}

// ---------------- initial diag (idx 0) ----------------
extern "C" __global__ void k_diag0()
{
    __shared__ float Lf[1056];
    __shared__ float rinvs[32];
    const int m = blockIdx.x, lane = threadIdx.x;
    const float* cov = g_cov + (size_t)m * NN * LDA;
    float a[32];
    #pragma unroll
    for (int j = 0; j < 32; ++j)
        a[j] = (j <= lane) ? cov[(size_t)lane * LDA + j] : 0.f;
    factor_store(a, lane, Lf, rinvs,
                 g_ld + ((size_t)m * 32) * 1056, g_ldet + m * 32);
    __syncwarp();
    invert_store(lane, Lf, rinvs,
                 g_iH + ((size_t)m * 32) * 1024, g_iL + ((size_t)m * 32) * 1024);
}

// ---------------- panel1: X = A * invL1^T  (grid: (ceil(ntiles/8), MM), 256 thr) ----------------
extern "C" __global__ void __launch_bounds__(256, 2)
k_panel1(int kb)
{
    __shared__ float Bbs[1056];
    __shared__ float Lf[1056];
    __shared__ float rinvs[32];
    const int m = blockIdx.y, pid = blockIdx.x, tid = threadIdx.x;
    const int wid = tid >> 5, lane = tid & 31;
    const int g = lane >> 2, t = lane & 3;
    const int k0 = kb * 64;
    const int ntiles = (NN - k0 - 32) >> 5;
    const int ti = pid * 8 + wid;
    float* cov = g_cov + (size_t)m * NN * LDA;
    uint16_t* gH = g_pH + (size_t)m * NN * PP;
    uint16_t* gL = g_pL + (size_t)m * NN * PP;
    const uint16_t* iH = g_iH + ((size_t)m * 32 + 2 * kb) * 1024;
    const uint16_t* iL = g_iL + ((size_t)m * 32 + 2 * kb) * 1024;

    if (ti < ntiles) {
        const int br = k0 + 32 + ti * 32;
        float c[2][4][4];
        #pragma unroll
        for (int mb = 0; mb < 2; ++mb)
            #pragma unroll
            for (int nb = 0; nb < 4; ++nb)
                #pragma unroll
                for (int q = 0; q < 4; ++q) c[mb][nb][q] = 0.f;

        #pragma unroll
        for (int kc = 0; kc < 32; kc += 16) {
            uint32_t aH[2][4], aL[2][4], bH[4][2], bL[4][2];
            #pragma unroll
            for (int mb = 0; mb < 2; ++mb) {
                int r = br + mb * 16 + g;
                float2 f;
                f = *(const float2*)&cov[(size_t)r * LDA + k0 + kc + 2*t];
                cvt2(f.x, f.y, aH[mb][0], aL[mb][0]);
                f = *(const float2*)&cov[(size_t)(r + 8) * LDA + k0 + kc + 2*t];
                cvt2(f.x, f.y, aH[mb][1], aL[mb][1]);
                f = *(const float2*)&cov[(size_t)r * LDA + k0 + kc + 2*t + 8];
                cvt2(f.x, f.y, aH[mb][2], aL[mb][2]);
                f = *(const float2*)&cov[(size_t)(r + 8) * LDA + k0 + kc + 2*t + 8];
                cvt2(f.x, f.y, aH[mb][3], aL[mb][3]);
            }
            #pragma unroll
            for (int nb = 0; nb < 4; ++nb) {
                int n = nb * 8 + g;
                bH[nb][0] = *(const uint32_t*)(iH + n * 32 + kc + 2*t);
                bH[nb][1] = *(const uint32_t*)(iH + n * 32 + kc + 2*t + 8);
                bL[nb][0] = *(const uint32_t*)(iL + n * 32 + kc + 2*t);
                bL[nb][1] = *(const uint32_t*)(iL + n * 32 + kc + 2*t + 8);
            }
            #pragma unroll
            for (int mb = 0; mb < 2; ++mb)
                #pragma unroll
                for (int nb = 0; nb < 4; ++nb) {
                    hmma(c[mb][nb], aH[mb], bH[nb]);
                    hmma(c[mb][nb], aH[mb], bL[nb]);
                    hmma(c[mb][nb], aL[mb], bH[nb]);
                }
        }
        // epilogue: X -> cov fp32 + planes bf16 (cb=0)
        #pragma unroll
        for (int mb = 0; mb < 2; ++mb)
            #pragma unroll
            for (int half = 0; half < 2; ++half) {
                int r = br + mb * 16 + g + half * 8;
                float* rowp = cov + (size_t)r * LDA + k0;
                uint16_t* hp = gH + (size_t)r * PP;
                uint16_t* lp = gL + (size_t)r * PP;
                #pragma unroll
                for (int nb = 0; nb < 4; ++nb) {
                    float2 v = make_float2(c[mb][nb][half*2], c[mb][nb][half*2+1]);
                    *(float2*)(rowp + nb*8 + 2*t) = v;
                    uint32_t h, l; cvt2(v.x, v.y, h, l);
                    *(uint32_t*)(hp + nb*8 + 2*t) = h;
                    *(uint32_t*)(lp + nb*8 + 2*t) = l;
                }
            }
    }

    // ---- block 0: diag2 = raw D2 - Bb*Bb^T, factor + invert ----
    if (pid == 0) {
        __syncthreads();
        if (wid == 0) {
            float bb[32];
            const float* brow = cov + (size_t)(k0 + 32 + lane) * LDA + k0;
            #pragma unroll
            for (int j = 0; j < 32; ++j) { bb[j] = brow[j]; Bbs[lane * 33 + j] = bb[j]; }
            __syncwarp();
            float a[32];
            const float* drow = cov + (size_t)(k0 + 32 + lane) * LDA + k0 + 32;
            #pragma unroll
            for (int cc = 0; cc < 32; ++cc) {
                float s = 0.f;
                if (cc <= lane) {
                    s = drow[cc];
                    #pragma unroll
                    for (int p = 0; p < 32; ++p) s -= bb[p] * Bbs[cc * 33 + p];
                }
                a[cc] = s;
            }
            factor_store(a, lane, Lf, rinvs,
                         g_ld + ((size_t)m * 32 + 2*kb + 1) * 1056,
                         g_ldet + m * 32 + 2*kb + 1);
            __syncwarp();
            invert_store(lane, Lf, rinvs,
                         g_iH + ((size_t)m * 32 + 2*kb + 1) * 1024,
                         g_iL + ((size_t)m * 32 + 2*kb + 1) * 1024);
        }
    }
}

// ---------------- panel2: X2 = (W - A*Bb^T) * invL2^T ----------------
extern "C" __global__ void __launch_bounds__(256, 2)
k_panel2(int kb)
{
    const int m = blockIdx.y, pid = blockIdx.x, tid = threadIdx.x;
    const int wid = tid >> 5, lane = tid & 31;
    const int g = lane >> 2, t = lane & 3;
    const int k0 = kb * 64;
    const int ntiles = (NN - k0 - 64) >> 5;
    const int ti = pid * 8 + wid;
    if (ti >= ntiles) return;
    const int br = k0 + 64 + ti * 32;
    float* cov = g_cov + (size_t)m * NN * LDA;
    uint16_t* gH = g_pH + (size_t)m * NN * PP;
    uint16_t* gL = g_pL + (size_t)m * NN * PP;
    const uint16_t* iH = g_iH + ((size_t)m * 32 + 2*kb + 1) * 1024;
    const uint16_t* iL = g_iL + ((size_t)m * 32 + 2*kb + 1) * 1024;

    // c = W (cols k0+32..63)
    float c[2][4][4];
    #pragma unroll
    for (int mb = 0; mb < 2; ++mb)
        #pragma unroll
        for (int half = 0; half < 2; ++half) {
            const float* rowp = cov + (size_t)(br + mb*16 + g + half*8) * LDA + k0 + 32;
            #pragma unroll
            for (int nb = 0; nb < 4; ++nb) {
                float2 w = *(const float2*)(rowp + nb*8 + 2*t);
                c[mb][nb][half*2]     = w.x;
                c[mb][nb][half*2 + 1] = w.y;
            }
        }

    // c -= A * Bb^T   (A negated via sign flip)
    #pragma unroll
    for (int kc = 0; kc < 32; kc += 16) {
        uint32_t aH[2][4], aL[2][4], bH[4][2], bL[4][2];
        #pragma unroll
        for (int mb = 0; mb < 2; ++mb) {
            size_t r0 = (size_t)(br + mb*16 + g) * PP + kc + 2*t;
            size_t r8 = r0 + 8 * PP;
            aH[mb][0] = *(const uint32_t*)(g_pH + (size_t)m*NN*PP + r0) ^ 0x80008000u;
            aH[mb][1] = *(const uint32_t*)(g_pH + (size_t)m*NN*PP + r8) ^ 0x80008000u;
            aH[mb][2] = *(const uint32_t*)(g_pH + (size_t)m*NN*PP + r0 + 8) ^ 0x80008000u;
            aH[mb][3] = *(const uint32_t*)(g_pH + (size_t)m*NN*PP + r8 + 8) ^ 0x80008000u;
            aL[mb][0] = *(const uint32_t*)(g_pL + (size_t)m*NN*PP + r0) ^ 0x80008000u;
            aL[mb][1] = *(const uint32_t*)(g_pL + (size_t)m*NN*PP + r8) ^ 0x80008000u;
            aL[mb][2] = *(const uint32_t*)(g_pL + (size_t)m*NN*PP + r0 + 8) ^ 0x80008000u;
            aL[mb][3] = *(const uint32_t*)(g_pL + (size_t)m*NN*PP + r8 + 8) ^ 0x80008000u;
        }
        #pragma unroll
        for (int nb = 0; nb < 4; ++nb) {
            size_t rj = (size_t)(k0 + 32 + nb*8 + g) * PP + kc + 2*t;
            bH[nb][0] = *(const uint32_t*)(gH + rj);
            bH[nb][1] = *(const uint32_t*)(gH + rj + 8);
            bL[nb][0] = *(const uint32_t*)(gL + rj);
            bL[nb][1] = *(const uint32_t*)(gL + rj + 8);
        }
        #pragma unroll
        for (int mb = 0; mb < 2; ++mb)
            #pragma unroll
            for (int nb = 0; nb < 4; ++nb) {
                hmma(c[mb][nb], aH[mb], bH[nb]);
                hmma(c[mb][nb], aH[mb], bL[nb]);
                hmma(c[mb][nb], aL[mb], bH[nb]);
            }
    }

    // stage 2: X2 = U * invL2^T  (a-frags remapped from c)
    float c2[2][4][4];
    #pragma unroll
    for (int mb = 0; mb < 2; ++mb)
        #pragma unroll
        for (int nb = 0; nb < 4; ++nb)
            #pragma unroll
            for (int q = 0; q < 4; ++q) c2[mb][nb][q] = 0.f;

    #pragma unroll
    for (int kx = 0; kx < 2; ++kx) {       // k-chunk = 16*kx
        uint32_t aH[2][4], aL[2][4], bH[4][2], bL[4][2];
        #pragma unroll
        for (int mb = 0; mb < 2; ++mb) {
            int n0 = 2 * kx, n1 = n0 + 1;
            cvt2(c[mb][n0][0], c[mb][n0][1], aH[mb][0], aL[mb][0]);
            cvt2(c[mb][n0][2], c[mb][n0][3], aH[mb][1], aL[mb][1]);
            cvt2(c[mb][n1][0], c[mb][n1][1], aH[mb][2], aL[mb][2]);
            cvt2(c[mb][n1][2], c[mb][n1][3], aH[mb][3], aL[mb][3]);
        }
        #pragma unroll
        for (int nb = 0; nb < 4; ++nb) {
            int n = nb * 8 + g;
            bH[nb][0] = *(const uint32_t*)(iH + n * 32 + 16*kx + 2*t);
            bH[nb][1] = *(const uint32_t*)(iH + n * 32 + 16*kx + 2*t + 8);
            bL[nb][0] = *(const uint32_t*)(iL + n * 32 + 16*kx + 2*t);
            bL[nb][1] = *(const uint32_t*)(iL + n * 32 + 16*kx + 2*t + 8);
        }
        #pragma unroll
        for (int mb = 0; mb < 2; ++mb)
            #pragma unroll
            for (int nb = 0; nb < 4; ++nb) {
                hmma(c2[mb][nb], aH[mb], bH[nb]);
                hmma(c2[mb][nb], aH[mb], bL[nb]);
                hmma(c2[mb][nb], aL[mb], bH[nb]);
            }
    }

    // epilogue
    #pragma unroll
    for (int mb = 0; mb < 2; ++mb)
        #pragma unroll
        for (int half = 0; half < 2; ++half) {
            int r = br + mb*16 + g + half*8;
            float* rowp = cov + (size_t)r * LDA + k0 + 32;
            uint16_t* hp = gH + (size_t)r * PP + 32;
            uint16_t* lp = gL + (size_t)r * PP + 32;
            #pragma unroll
            for (int nb = 0; nb < 4; ++nb) {
                float2 v = make_float2(c2[mb][nb][half*2], c2[mb][nb][half*2+1]);
                *(float2*)(rowp + nb*8 + 2*t) = v;
                uint32_t h, l; cvt2(v.x, v.y, h, l);
                *(uint32_t*)(hp + nb*8 + 2*t) = h;
                *(uint32_t*)(lp + nb*8 + 2*t) = l;
            }
        }
}

// ---------------- trailing K=64 update + next diag1 ----------------
extern "C" __global__ void __launch_bounds__(256, 2)
k_trail(int kb)
{
    __shared__ float Lf[1056];
    __shared__ float rinvs[32];
    const int m = blockIdx.y, tid = threadIdx.x;
    const int wid = tid >> 5, lane = tid & 31;
    const int k0 = kb * 64;
    const int nt = NN - k0 - 64;
    const int ntile = nt >> 5;
    const int npair = ntile * (ntile + 1) / 2;
    const int pair = blockIdx.x * 8 + wid;
    if (pair >= npair) return;

    float* cov = g_cov + (size_t)m * NN * LDA;
    const uint16_t* gH = g_pH + (size_t)m * NN * PP;
    const uint16_t* gL = g_pL + (size_t)m * NN * PP;
    const int g = lane >> 2, t = lane & 3;
    const int g0 = k0 + 64;

    int tib = 0, rem = pair;
    while (rem >= tib + 1) { rem -= tib + 1; ++tib; }
    const int tjb = rem;
    const int i0 = tib * 32, j0 = tjb * 32;
    const bool full = (tib != tjb);

    float2 cp[2][2][4];
    if (full) {
        #pragma unroll
        for (int mb = 0; mb < 2; ++mb)
            #pragma unroll
            for (int half = 0; half < 2; ++half) {
                const float* rowp = cov + (size_t)(g0 + i0 + mb*16 + g + half*8) * LDA + g0 + j0;
                #pragma unroll
                for (int nb = 0; nb < 4; ++nb)
                    cp[mb][half][nb] = *(const float2*)(rowp + nb*8 + t*2);
            }
    }

    float c[2][4][4];
    #pragma unroll
    for (int mb = 0; mb < 2; ++mb)
        #pragma unroll
        for (int nb = 0; nb < 4; ++nb)
            #pragma unroll
            for (int q = 0; q < 4; ++q) c[mb][nb][q] = 0.f;

    #pragma unroll
    for (int kc = 0; kc < 64; kc += 16) {
        uint32_t aH[2][4], aL[2][4], bH[4][2], bL[4][2];
        #pragma unroll
        for (int mb = 0; mb < 2; ++mb) {
            size_t r0 = (size_t)(g0 + i0 + mb*16 + g) * PP + kc + 2*t;
            size_t r8 = r0 + 8 * PP;
            aH[mb][0] = *(const uint32_t*)(gH + r0);
            aH[mb][1] = *(const uint32_t*)(gH + r8);
            aH[mb][2] = *(const uint32_t*)(gH + r0 + 8);
            aH[mb][3] = *(const uint32_t*)(gH + r8 + 8);
            aL[mb][0] = *(const uint32_t*)(gL + r0);
            aL[mb][1] = *(const uint32_t*)(gL + r8);
            aL[mb][2] = *(const uint32_t*)(gL + r0 + 8);
            aL[mb][3] = *(const uint32_t*)(gL + r8 + 8);
        }
        #pragma unroll
        for (int nb = 0; nb < 4; ++nb) {
            size_t rj = (size_t)(g0 + j0 + nb*8 + g) * PP + kc + 2*t;
            bH[nb][0] = *(const uint32_t*)(gH + rj);
            bH[nb][1] = *(const uint32_t*)(gH + rj + 8);
            bL[nb][0] = *(const uint32_t*)(gL + rj);
            bL[nb][1] = *(const uint32_t*)(gL + rj + 8);
        }
        #pragma unroll
        for (int mb = 0; mb < 2; ++mb)
            #pragma unroll
            for (int nb = 0; nb < 4; ++nb) {
                hmma(c[mb][nb], aH[mb], bH[nb]);
                hmma(c[mb][nb], aH[mb], bL[nb]);
                hmma(c[mb][nb], aL[mb], bH[nb]);
            }
    }

    if (full) {
        #pragma unroll
        for (int mb = 0; mb < 2; ++mb)
            #pragma unroll
            for (int half = 0; half < 2; ++half) {
                float* rowp = cov + (size_t)(g0 + i0 + mb*16 + g + half*8) * LDA + g0 + j0;
                #pragma unroll
                for (int nb = 0; nb < 4; ++nb) {
                    float2 v = cp[mb][half][nb];
                    v.x -= c[mb][nb][half*2];
                    v.y -= c[mb][nb][half*2 + 1];
                    *(float2*)(rowp + nb*8 + t*2) = v;
                }
            }
    } else {
        #pragma unroll
        for (int mb = 0; mb < 2; ++mb)
            #pragma unroll
            for (int half = 0; half < 2; ++half) {
                int i_loc = i0 + mb*16 + g + half*8;
                float* row = cov + (size_t)(g0 + i_loc) * LDA + g0;
                #pragma unroll
                for (int nb = 0; nb < 4; ++nb) {
                    int j = j0 + nb*8 + t*2;
                    float cx = c[mb][nb][half*2];
                    float cy = c[mb][nb][half*2 + 1];
                    if (j + 1 <= i_loc) {
                        float2 v = *(float2*)(row + j);
                        v.x -= cx; v.y -= cy;
                        *(float2*)(row + j) = v;
                    } else if (j <= i_loc) {
                        row[j] -= cx;
                    }
                }
            }
    }

    // pair 0 warp: factor + invert next step's diag1 (updated tile (0,0))
    if (pair == 0) {
        __threadfence_block();
        __syncwarp();
        float a[32];
        const float* rr = cov + (size_t)(g0 + lane) * LDA + g0;
        #pragma unroll
        for (int j = 0; j < 32; ++j)
            a[j] = (j <= lane) ? rr[j] : 0.f;
        factor_store(a, lane, Lf, rinvs,
                     g_ld + ((size_t)m * 32 + 2*(kb+1)) * 1056,
                     g_ldet + m * 32 + 2*(kb+1));
        __syncwarp();
        invert_store(lane, Lf, rinvs,
                     g_iH + ((size_t)m * 32 + 2*(kb+1)) * 1024,
                     g_iL + ((size_t)m * 32 + 2*(kb+1)) * 1024);
    }
}

// ---------------- forward substitution + output (grid: MM) ----------------
extern "C" __global__ void __launch_bounds__(512, 1)
k_finish(const float* __restrict__ y, float* __restrict__ out)
{
    __shared__ float rhs[NN];
    __shared__ float red[512];
    const int m = blockIdx.x, tid = threadIdx.x, lane = tid & 31;
    float* cov = g_cov + (size_t)m * NN * LDA;
    const float beta = g_scal[m*8+0];

    for (int i = tid; i < NN; i += 512) rhs[i] = y[i] - beta;
    __syncthreads();

    for (int kb2 = 0; kb2 < 32; ++kb2) {
        const int k0 = kb2 * 32;
        if (tid < 32) {
            const float* lrow = g_ld + ((size_t)m * 32 + kb2) * 1056 + lane * 33;
            float lr[32];
            #pragma unroll
            for (int j = 0; j < 32; ++j) lr[j] = lrow[j];
            float t = rhs[k0 + lane];
            #pragma unroll
            for (int j = 0; j < 32; ++j) {
                if (lane == j) t /= lr[j];
                float sj = __shfl_sync(0xffffffffu, t, j);
                if (lane > j) t -= sj * lr[j];
            }
            rhs[k0 + lane] = t;
        }
        __syncthreads();
        for (int i = k0 + 32 + tid; i < NN; i += 512) {
            const float* row = cov + (size_t)i * LDA + k0;
            float acc = 0.f;
            #pragma unroll
            for (int w = 0; w < 8; ++w) {
                float4 c4 = ((const float4*)row)[w];
                acc += c4.x * rhs[k0 + 4*w]     + c4.y * rhs[k0 + 4*w + 1]
                     + c4.z * rhs[k0 + 4*w + 2] + c4.w * rhs[k0 + 4*w + 3];
            }
            rhs[i] -= acc;
        }
        __syncthreads();
    }

    float q = 0.f;
    for (int i = tid; i < NN; i += 512) { float v = rhs[i]; q += v * v; }
    red[tid] = q;
    __syncthreads();
    for (int s = 256; s; s >>= 1) {
        if (tid < s) red[tid] += red[tid + s];
        __syncthreads();
    }
    if (tid == 0) {
        float ldsum = 0.f;
        for (int d = 0; d < 32; ++d) ldsum += g_ldet[m * 32 + d];
        const float LN2PI = 1.8378770664093453f;
        out[m] = -0.5f * (red[0] + 2.f * ldsum + 1024.f * LN2PI) + g_scal[m*8+5];
    }
}

extern "C" void kernel_launch(void* const* d_in, const int* in_sizes, int n_in,
                              void* d_out, int out_size)
{
    (void)in_sizes; (void)n_in; (void)out_size;
    const float* x = (const float*)d_in[0];
    const float* y = (const float*)d_in[1];
    const float* z = (const float*)d_in[2];

    k_scal<<<MM, 32>>>(z,
        (const float*)d_in[3], (const float*)d_in[4],
        (const float*)d_in[5], (const float*)d_in[6],
        (const float*)d_in[7], (const float*)d_in[8],
        (const float*)d_in[9], (const float*)d_in[10],
        (const float*)d_in[11], (const float*)d_in[12]);
    k_build<<<dim3(2, MM), 512>>>(x);
    k_diag0<<<MM, 32>>>();

    for (int kb = 0; kb < 16; ++kb) {
        int nt1 = 31 - 2 * kb;
        k_panel1<<<dim3((nt1 + 7) / 8, MM), 256>>>(kb);
        int nt2 = 30 - 2 * kb;
        if (nt2 > 0) {
            k_panel2<<<dim3((nt2 + 7) / 8, MM), 256>>>(kb);
            int npair = nt2 * (nt2 + 1) / 2;
            k_trail<<<dim3((npair + 7) / 8, MM), 256>>>(kb);
        }
    }
    k_finish<<<MM, 512>>>(y, (float*)d_out);
}

// round 14
// speedup vs baseline: 1.1547x; 1.0025x over previous
#include <cuda_runtime.h>
#include <cuda_bf16.h>
#include <math.h>
#include <stdint.h>

#define NN 1024
#define MM 64
#define LDA 1040
#define PP 64               // pitch of bf16 panel planes

__device__ float    g_cov[(size_t)MM * NN * LDA];
__device__ uint16_t g_pH[(size_t)MM * NN * PP];
__device__ uint16_t g_pL[(size_t)MM * NN * PP];
__device__ float    g_ld[(size_t)MM * 32 * 1056];    // factored diag blocks (33-pitch, lower)
__device__ uint16_t g_iH[(size_t)MM * 32 * 1024];    // inv(L) bf16 hi, 32x32 row-major
__device__ uint16_t g_iL[(size_t)MM * 32 * 1024];    // inv(L) bf16 lo
__device__ float    g_scal[MM * 8];
__device__ float    g_ldet[MM * 32];

__device__ __forceinline__ void hmma(float* c, const uint32_t* a, const uint32_t* b) {
    asm volatile("mma.sync.aligned.m16n8k16.row.col.f32.bf16.bf16.f32 "
        "{%0,%1,%2,%3},{%4,%5,%6,%7},{%8,%9},{%0,%1,%2,%3};"
        : "+f"(c[0]), "+f"(c[1]), "+f"(c[2]), "+f"(c[3])
        : "r"(a[0]), "r"(a[1]), "r"(a[2]), "r"(a[3]), "r"(b[0]), "r"(b[1]));
}
__device__ __forceinline__ void cvt2(float xx, float yy, uint32_t& h, uint32_t& l) {
    __nv_bfloat16 h0 = __float2bfloat16(xx), h1 = __float2bfloat16(yy);
    __nv_bfloat16 l0 = __float2bfloat16(xx - __bfloat162float(h0));
    __nv_bfloat16 l1 = __float2bfloat16(yy - __bfloat162float(h1));
    h = (uint32_t)__bfloat16_as_ushort(h0) | ((uint32_t)__bfloat16_as_ushort(h1) << 16);
    l = (uint32_t)__bfloat16_as_ushort(l0) | ((uint32_t)__bfloat16_as_ushort(l1) << 16);
}
__device__ __forceinline__ float sp_(float x) {
    return fmaxf(x, 0.f) + log1pf(expf(-fabsf(x))) + 1e-7f;
}
__device__ __forceinline__ float log_normal_(float v, float mean, float s, float eps) {
    const float C = -0.91893853320467274178f;
    float d = v - mean;
    return -d * d / (2.f * s * s + eps) - logf(s) + C;
}
__device__ __forceinline__ float log_lognormal_(float v, float mean, float s, float eps) {
    const float C = -0.91893853320467274178f;
    float lv = logf(v);
    float d = lv - mean;
    return -d * d / (2.f * s * s + eps) - lv - logf(s) + C;
}
__device__ __forceinline__ void compute_scal(const float* z, int m,
    const float* qbm, const float* qbs, const float* qsm, const float* qss,
    const float* qem, const float* qes, const float* qzm, const float* qzs,
    const float* qnm, const float* qns, float* out8)
{
    float s0 = sp_(sqrtf(logf(2.f)));
    float z0 = z[m*5+0], z1 = z[m*5+1], z2 = z[m*5+2], z3 = z[m*5+3], z4 = z[m*5+4];
    float sps = sp_(*qss), spb = sp_(*qbs), spe = sp_(*qes), spz = sp_(*qzs), spn = sp_(*qns);
    float sigma2 = expf(z0 * sps + *qsm);
    float beta   = z1 * spb + *qbm;
    float eta    = expf(z2 * spe + *qem);
    float lsZ    = expf(z3 * spz + *qzm);
    float lsN    = expf(z4 * spn + *qnm);
    float lp = log_normal_(beta, 0.f, 1.f, 1e-5f)
             + log_lognormal_(sigma2, 1.f, s0, 1e-6f)
             + log_lognormal_(eta,    1.f, s0, 1e-6f)
             + log_lognormal_(lsZ,    1.f, s0, 1e-6f)
             + log_lognormal_(lsN,    1.f, s0, 1e-6f);
    float lq = log_normal_(beta, *qbm, spb, 1e-5f)
             + log_lognormal_(sigma2, *qsm, sps, 1e-6f)
             + log_lognormal_(eta,    *qem, spe, 1e-6f)
             + log_lognormal_(lsZ,    *qzm, spz, 1e-6f)
             + log_lognormal_(lsN,    *qnm, spn, 1e-6f);
    out8[0] = beta; out8[1] = sigma2; out8[2] = eta;
    out8[3] = lsZ;  out8[4] = lsN;    out8[5] = lp - lq;
}

// factor a[32] (lane = row; a[j]=0 for j>lane on entry)
__device__ __forceinline__ void factor_store(float* a, int lane, float* Lf, float* rinvs,
                                             float* gld, float* ldet_out)
{
    #pragma unroll
    for (int j = 0; j < 32; ++j) {
        float dj = __shfl_sync(0xffffffffu, a[j], j);
        float sj = sqrtf(dj);
        float lrj = (lane == j) ? sj : a[j] / sj;
        a[j] = lrj;
        #pragma unroll
        for (int cc = j + 1; cc < 32; ++cc)
            a[cc] -= lrj * __shfl_sync(0xffffffffu, lrj, cc);
    }
    #pragma unroll
    for (int j = 0; j < 32; ++j) {
        float v = (j <= lane) ? a[j] : 0.f;
        Lf[lane * 33 + j] = v;
        gld[lane * 33 + j] = v;
    }
    rinvs[lane] = 1.f / a[lane];
    float ld = logf(a[lane]);
    #pragma unroll
    for (int o = 16; o; o >>= 1) ld += __shfl_xor_sync(0xffffffffu, ld, o);
    if (lane == 0) *ldet_out = ld;
}

// lane j computes column j of inv(L); stores bf16 hi/lo
__device__ __forceinline__ void invert_store(int lane, const float* Lf, const float* rinvs,
                                             uint16_t* oH, uint16_t* oL)
{
    float xv[32];
    #pragma unroll
    for (int i = 0; i < 32; ++i) {
        float s = (i == lane) ? 1.f : 0.f;
        #pragma unroll
        for (int p = 0; p < 31; ++p)
            if (p < i) s -= Lf[i * 33 + p] * xv[p];
        xv[i] = s * rinvs[i];
    }
    #pragma unroll
    for (int i = 0; i < 32; ++i) {
        __nv_bfloat16 h = __float2bfloat16(xv[i]);
        __nv_bfloat16 l = __float2bfloat16(xv[i] - __bfloat162float(h));
        oH[i * 32 + lane] = __bfloat16_as_ushort(h);
        oL[i * 32 + lane] = __bfloat16_as_ushort(l);
    }
}

// ---------------- cov build + scalars (grid: (2, MM)) ----------------
extern "C" __global__ void __launch_bounds__(512, 1)
k_build(const float* __restrict__ x, const float* __restrict__ z,
    const float* qbm, const float* qbs, const float* qsm, const float* qss,
    const float* qem, const float* qes, const float* qzm, const float* qzs,
    const float* qnm, const float* qns)
{
    __shared__ float xs[2048];
    __shared__ float sc[8];
    const int m = blockIdx.y, par = blockIdx.x, tid = threadIdx.x;
    float* cov = g_cov + (size_t)m * NN * LDA;
    if (tid == 0) {
        compute_scal(z, m, qbm, qbs, qsm, qss, qem, qes, qzm, qzs, qnm, qns, sc);
        if (par == 0) {
            #pragma unroll
            for (int q = 0; q < 6; ++q) g_scal[m*8+q] = sc[q];
        }
    }
    __syncthreads();
    const float eta = sc[2], sigma2 = sc[1], lsZ = sc[3], lsN = sc[4];
    for (int i = tid; i < NN; i += 512) {
        xs[i]      = x[2*i]   / lsZ;
        xs[NN + i] = x[2*i+1] / lsN;
    }
    __syncthreads();
    const float* xs0 = xs;
    const float* xs1 = xs + NN;
    int i = par + 2 * tid;
    float xi0 = xs0[i], xi1 = xs1[i];
    float* row = cov + (size_t)i * LDA;
    int j4 = i & ~3;
    for (int j = 0; j < j4; j += 4) {
        float4 a0 = *(const float4*)(xs0 + j);
        float4 a1 = *(const float4*)(xs1 + j);
        float4 o; float d0, d1;
        d0 = xi0 - a0.x; d1 = xi1 - a1.x; o.x = eta * __expf(-0.5f * (d0*d0 + d1*d1));
        d0 = xi0 - a0.y; d1 = xi1 - a1.y; o.y = eta * __expf(-0.5f * (d0*d0 + d1*d1));
        d0 = xi0 - a0.z; d1 = xi1 - a1.z; o.z = eta * __expf(-0.5f * (d0*d0 + d1*d1));
        d0 = xi0 - a0.w; d1 = xi1 - a1.w; o.w = eta * __expf(-0.5f * (d0*d0 + d1*d1));
        *(float4*)(row + j) = o;
    }
    for (int j = j4; j < i; ++j) {
        float d0 = xi0 - xs0[j], d1 = xi1 - xs1[j];
        row[j] = eta * __expf(-0.5f * (d0*d0 + d1*d1));
    }
    row[i] = eta + sigma2;
}

// ---------------- initial diag (idx 0) ----------------
extern "C" __global__ void k_diag0()
{
    __shared__ float Lf[1056];
    __shared__ float rinvs[32];
    const int m = blockIdx.x, lane = threadIdx.x;
    const float* cov = g_cov + (size_t)m * NN * LDA;
    float a[32];
    #pragma unroll
    for (int j = 0; j < 32; ++j)
        a[j] = (j <= lane) ? cov[(size_t)lane * LDA + j] : 0.f;
    factor_store(a, lane, Lf, rinvs,
                 g_ld + ((size_t)m * 32) * 1056, g_ldet + m * 32);
    __syncwarp();
    invert_store(lane, Lf, rinvs,
                 g_iH + ((size_t)m * 32) * 1024, g_iL + ((size_t)m * 32) * 1024);
}

// ---------------- panel1: X = A * invL1^T ; warp0/block0 also does diag2 ----------------
extern "C" __global__ void __launch_bounds__(256, 2)
k_panel1(int kb)
{
    __shared__ float Bbs[1056];
    __shared__ float Lf[1056];
    __shared__ float rinvs[32];
    const int m = blockIdx.y, pid = blockIdx.x, tid = threadIdx.x;
    const int wid = tid >> 5, lane = tid & 31;
    const int g = lane >> 2, t = lane & 3;
    const int k0 = kb * 64;
    const int ntiles = (NN - k0 - 32) >> 5;
    const int ti = pid * 8 + wid;
    float* cov = g_cov + (size_t)m * NN * LDA;
    uint16_t* gH = g_pH + (size_t)m * NN * PP;
    uint16_t* gL = g_pL + (size_t)m * NN * PP;
    const uint16_t* iH = g_iH + ((size_t)m * 32 + 2 * kb) * 1024;
    const uint16_t* iL = g_iL + ((size_t)m * 32 + 2 * kb) * 1024;

    const bool do_diag2 = (pid == 0 && wid == 0);

    if (ti < ntiles) {
        const int br = k0 + 32 + ti * 32;
        float c[2][4][4];
        #pragma unroll
        for (int mb = 0; mb < 2; ++mb)
            #pragma unroll
            for (int nb = 0; nb < 4; ++nb)
                #pragma unroll
                for (int q = 0; q < 4; ++q) c[mb][nb][q] = 0.f;

        #pragma unroll
        for (int kc = 0; kc < 32; kc += 16) {
            uint32_t aH[2][4], aL[2][4], bH[4][2], bL[4][2];
            #pragma unroll
            for (int mb = 0; mb < 2; ++mb) {
                int r = br + mb * 16 + g;
                float2 f;
                f = *(const float2*)&cov[(size_t)r * LDA + k0 + kc + 2*t];
                cvt2(f.x, f.y, aH[mb][0], aL[mb][0]);
                f = *(const float2*)&cov[(size_t)(r + 8) * LDA + k0 + kc + 2*t];
                cvt2(f.x, f.y, aH[mb][1], aL[mb][1]);
                f = *(const float2*)&cov[(size_t)r * LDA + k0 + kc + 2*t + 8];
                cvt2(f.x, f.y, aH[mb][2], aL[mb][2]);
                f = *(const float2*)&cov[(size_t)(r + 8) * LDA + k0 + kc + 2*t + 8];
                cvt2(f.x, f.y, aH[mb][3], aL[mb][3]);
            }
            #pragma unroll
            for (int nb = 0; nb < 4; ++nb) {
                int n = nb * 8 + g;
                bH[nb][0] = *(const uint32_t*)(iH + n * 32 + kc + 2*t);
                bH[nb][1] = *(const uint32_t*)(iH + n * 32 + kc + 2*t + 8);
                bL[nb][0] = *(const uint32_t*)(iL + n * 32 + kc + 2*t);
                bL[nb][1] = *(const uint32_t*)(iL + n * 32 + kc + 2*t + 8);
            }
            #pragma unroll
            for (int mb = 0; mb < 2; ++mb)
                #pragma unroll
                for (int nb = 0; nb < 4; ++nb) {
                    hmma(c[mb][nb], aH[mb], bH[nb]);
                    hmma(c[mb][nb], aH[mb], bL[nb]);
                    hmma(c[mb][nb], aL[mb], bH[nb]);
                }
        }
        // epilogue: X -> cov fp32 + planes bf16 (cb=0)
        #pragma unroll
        for (int mb = 0; mb < 2; ++mb)
            #pragma unroll
            for (int half = 0; half < 2; ++half) {
                int r = br + mb * 16 + g + half * 8;
                float* rowp = cov + (size_t)r * LDA + k0;
                uint16_t* hp = gH + (size_t)r * PP;
                uint16_t* lp = gL + (size_t)r * PP;
                #pragma unroll
                for (int nb = 0; nb < 4; ++nb) {
                    float2 v = make_float2(c[mb][nb][half*2], c[mb][nb][half*2+1]);
                    *(float2*)(rowp + nb*8 + 2*t) = v;
                    uint32_t h, l; cvt2(v.x, v.y, h, l);
                    *(uint32_t*)(hp + nb*8 + 2*t) = h;
                    *(uint32_t*)(lp + nb*8 + 2*t) = l;
                }
            }

        // warp0/block0: scatter X (tile 0 = Bb) into smem from registers, then diag2
        if (do_diag2) {
            #pragma unroll
            for (int mb = 0; mb < 2; ++mb)
                #pragma unroll
                for (int nb = 0; nb < 4; ++nb)
                    #pragma unroll
                    for (int q = 0; q < 4; ++q) {
                        int rr = mb * 16 + g + (q >> 1) * 8;
                        int ccol = nb * 8 + 2 * t + (q & 1);
                        Bbs[rr * 33 + ccol] = c[mb][nb][q];
                    }
            __syncwarp();
            float bb[32];
            #pragma unroll
            for (int j = 0; j < 32; ++j) bb[j] = Bbs[lane * 33 + j];
            float a[32];
            const float* drow = cov + (size_t)(k0 + 32 + lane) * LDA + k0 + 32;
            #pragma unroll
            for (int cc = 0; cc < 32; ++cc) {
                float s = 0.f;
                if (cc <= lane) {
                    s = drow[cc];
                    #pragma unroll
                    for (int p = 0; p < 32; ++p) s -= bb[p] * Bbs[cc * 33 + p];
                }
                a[cc] = s;
            }
            factor_store(a, lane, Lf, rinvs,
                         g_ld + ((size_t)m * 32 + 2*kb + 1) * 1056,
                         g_ldet + m * 32 + 2*kb + 1);
            __syncwarp();
            invert_store(lane, Lf, rinvs,
                         g_iH + ((size_t)m * 32 + 2*kb + 1) * 1024,
                         g_iL + ((size_t)m * 32 + 2*kb + 1) * 1024);
        }
    }
}

// ---------------- panel2: X2 = (W - A*Bb^T) * invL2^T ----------------
extern "C" __global__ void __launch_bounds__(256, 2)
k_panel2(int kb)
{
    const int m = blockIdx.y, pid = blockIdx.x, tid = threadIdx.x;
    const int wid = tid >> 5, lane = tid & 31;
    const int g = lane >> 2, t = lane & 3;
    const int k0 = kb * 64;
    const int ntiles = (NN - k0 - 64) >> 5;
    const int ti = pid * 8 + wid;
    if (ti >= ntiles) return;
    const int br = k0 + 64 + ti * 32;
    float* cov = g_cov + (size_t)m * NN * LDA;
    uint16_t* gH = g_pH + (size_t)m * NN * PP;
    uint16_t* gL = g_pL + (size_t)m * NN * PP;
    const uint16_t* iH = g_iH + ((size_t)m * 32 + 2*kb + 1) * 1024;
    const uint16_t* iL = g_iL + ((size_t)m * 32 + 2*kb + 1) * 1024;

    float c[2][4][4];
    #pragma unroll
    for (int mb = 0; mb < 2; ++mb)
        #pragma unroll
        for (int half = 0; half < 2; ++half) {
            const float* rowp = cov + (size_t)(br + mb*16 + g + half*8) * LDA + k0 + 32;
            #pragma unroll
            for (int nb = 0; nb < 4; ++nb) {
                float2 w = *(const float2*)(rowp + nb*8 + 2*t);
                c[mb][nb][half*2]     = w.x;
                c[mb][nb][half*2 + 1] = w.y;
            }
        }

    #pragma unroll
    for (int kc = 0; kc < 32; kc += 16) {
        uint32_t aH[2][4], aL[2][4], bH[4][2], bL[4][2];
        #pragma unroll
        for (int mb = 0; mb < 2; ++mb) {
            size_t r0 = (size_t)(br + mb*16 + g) * PP + kc + 2*t;
            size_t r8 = r0 + 8 * PP;
            aH[mb][0] = *(const uint32_t*)(gH + r0) ^ 0x80008000u;
            aH[mb][1] = *(const uint32_t*)(gH + r8) ^ 0x80008000u;
            aH[mb][2] = *(const uint32_t*)(gH + r0 + 8) ^ 0x80008000u;
            aH[mb][3] = *(const uint32_t*)(gH + r8 + 8) ^ 0x80008000u;
            aL[mb][0] = *(const uint32_t*)(gL + r0) ^ 0x80008000u;
            aL[mb][1] = *(const uint32_t*)(gL + r8) ^ 0x80008000u;
            aL[mb][2] = *(const uint32_t*)(gL + r0 + 8) ^ 0x80008000u;
            aL[mb][3] = *(const uint32_t*)(gL + r8 + 8) ^ 0x80008000u;
        }
        #pragma unroll
        for (int nb = 0; nb < 4; ++nb) {
            size_t rj = (size_t)(k0 + 32 + nb*8 + g) * PP + kc + 2*t;
            bH[nb][0] = *(const uint32_t*)(gH + rj);
            bH[nb][1] = *(const uint32_t*)(gH + rj + 8);
            bL[nb][0] = *(const uint32_t*)(gL + rj);
            bL[nb][1] = *(const uint32_t*)(gL + rj + 8);
        }
        #pragma unroll
        for (int mb = 0; mb < 2; ++mb)
            #pragma unroll
            for (int nb = 0; nb < 4; ++nb) {
                hmma(c[mb][nb], aH[mb], bH[nb]);
                hmma(c[mb][nb], aH[mb], bL[nb]);
                hmma(c[mb][nb], aL[mb], bH[nb]);
            }
    }

    float c2[2][4][4];
    #pragma unroll
    for (int mb = 0; mb < 2; ++mb)
        #pragma unroll
        for (int nb = 0; nb < 4; ++nb)
            #pragma unroll
            for (int q = 0; q < 4; ++q) c2[mb][nb][q] = 0.f;

    #pragma unroll
    for (int kx = 0; kx < 2; ++kx) {
        uint32_t aH[2][4], aL[2][4], bH[4][2], bL[4][2];
        #pragma unroll
        for (int mb = 0; mb < 2; ++mb) {
            int n0 = 2 * kx, n1 = n0 + 1;
            cvt2(c[mb][n0][0], c[mb][n0][1], aH[mb][0], aL[mb][0]);
            cvt2(c[mb][n0][2], c[mb][n0][3], aH[mb][1], aL[mb][1]);
            cvt2(c[mb][n1][0], c[mb][n1][1], aH[mb][2], aL[mb][2]);
            cvt2(c[mb][n1][2], c[mb][n1][3], aH[mb][3], aL[mb][3]);
        }
        #pragma unroll
        for (int nb = 0; nb < 4; ++nb) {
            int n = nb * 8 + g;
            bH[nb][0] = *(const uint32_t*)(iH + n * 32 + 16*kx + 2*t);
            bH[nb][1] = *(const uint32_t*)(iH + n * 32 + 16*kx + 2*t + 8);
            bL[nb][0] = *(const uint32_t*)(iL + n * 32 + 16*kx + 2*t);
            bL[nb][1] = *(const uint32_t*)(iL + n * 32 + 16*kx + 2*t + 8);
        }
        #pragma unroll
        for (int mb = 0; mb < 2; ++mb)
            #pragma unroll
            for (int nb = 0; nb < 4; ++nb) {
                hmma(c2[mb][nb], aH[mb], bH[nb]);
                hmma(c2[mb][nb], aH[mb], bL[nb]);
                hmma(c2[mb][nb], aL[mb], bH[nb]);
            }
    }

    #pragma unroll
    for (int mb = 0; mb < 2; ++mb)
        #pragma unroll
        for (int half = 0; half < 2; ++half) {
            int r = br + mb*16 + g + half*8;
            float* rowp = cov + (size_t)r * LDA + k0 + 32;
            uint16_t* hp = gH + (size_t)r * PP + 32;
            uint16_t* lp = gL + (size_t)r * PP + 32;
            #pragma unroll
            for (int nb = 0; nb < 4; ++nb) {
                float2 v = make_float2(c2[mb][nb][half*2], c2[mb][nb][half*2+1]);
                *(float2*)(rowp + nb*8 + 2*t) = v;
                uint32_t h, l; cvt2(v.x, v.y, h, l);
                *(uint32_t*)(hp + nb*8 + 2*t) = h;
                *(uint32_t*)(lp + nb*8 + 2*t) = l;
            }
        }
}

// ---------------- trailing K=64 update + next diag1 ----------------
extern "C" __global__ void __launch_bounds__(256, 2)
k_trail(int kb)
{
    __shared__ float Lf[1056];
    __shared__ float rinvs[32];
    const int m = blockIdx.y, tid = threadIdx.x;
    const int wid = tid >> 5, lane = tid & 31;
    const int k0 = kb * 64;
    const int nt = NN - k0 - 64;
    const int ntile = nt >> 5;
    const int npair = ntile * (ntile + 1) / 2;
    const int pair = blockIdx.x * 8 + wid;
    if (pair >= npair) return;

    float* cov = g_cov + (size_t)m * NN * LDA;
    const uint16_t* gH = g_pH + (size_t)m * NN * PP;
    const uint16_t* gL = g_pL + (size_t)m * NN * PP;
    const int g = lane >> 2, t = lane & 3;
    const int g0 = k0 + 64;

    int tib = 0, rem = pair;
    while (rem >= tib + 1) { rem -= tib + 1; ++tib; }
    const int tjb = rem;
    const int i0 = tib * 32, j0 = tjb * 32;
    const bool full = (tib != tjb);

    float2 cp[2][2][4];
    if (full) {
        #pragma unroll
        for (int mb = 0; mb < 2; ++mb)
            #pragma unroll
            for (int half = 0; half < 2; ++half) {
                const float* rowp = cov + (size_t)(g0 + i0 + mb*16 + g + half*8) * LDA + g0 + j0;
                #pragma unroll
                for (int nb = 0; nb < 4; ++nb)
                    cp[mb][half][nb] = *(const float2*)(rowp + nb*8 + t*2);
            }
    }

    float c[2][4][4];
    #pragma unroll
    for (int mb = 0; mb < 2; ++mb)
        #pragma unroll
        for (int nb = 0; nb < 4; ++nb)
            #pragma unroll
            for (int q = 0; q < 4; ++q) c[mb][nb][q] = 0.f;

    #pragma unroll
    for (int kc = 0; kc < 64; kc += 16) {
        uint32_t aH[2][4], aL[2][4], bH[4][2], bL[4][2];
        #pragma unroll
        for (int mb = 0; mb < 2; ++mb) {
            size_t r0 = (size_t)(g0 + i0 + mb*16 + g) * PP + kc + 2*t;
            size_t r8 = r0 + 8 * PP;
            aH[mb][0] = *(const uint32_t*)(gH + r0);
            aH[mb][1] = *(const uint32_t*)(gH + r8);
            aH[mb][2] = *(const uint32_t*)(gH + r0 + 8);
            aH[mb][3] = *(const uint32_t*)(gH + r8 + 8);
            aL[mb][0] = *(const uint32_t*)(gL + r0);
            aL[mb][1] = *(const uint32_t*)(gL + r8);
            aL[mb][2] = *(const uint32_t*)(gL + r0 + 8);
            aL[mb][3] = *(const uint32_t*)(gL + r8 + 8);
        }
        #pragma unroll
        for (int nb = 0; nb < 4; ++nb) {
            size_t rj = (size_t)(g0 + j0 + nb*8 + g) * PP + kc + 2*t;
            bH[nb][0] = *(const uint32_t*)(gH + rj);
            bH[nb][1] = *(const uint32_t*)(gH + rj + 8);
            bL[nb][0] = *(const uint32_t*)(gL + rj);
            bL[nb][1] = *(const uint32_t*)(gL + rj + 8);
        }
        #pragma unroll
        for (int mb = 0; mb < 2; ++mb)
            #pragma unroll
            for (int nb = 0; nb < 4; ++nb) {
                hmma(c[mb][nb], aH[mb], bH[nb]);
                hmma(c[mb][nb], aH[mb], bL[nb]);
                hmma(c[mb][nb], aL[mb], bH[nb]);
            }
    }

    if (full) {
        #pragma unroll
        for (int mb = 0; mb < 2; ++mb)
            #pragma unroll
            for (int half = 0; half < 2; ++half) {
                float* rowp = cov + (size_t)(g0 + i0 + mb*16 + g + half*8) * LDA + g0 + j0;
                #pragma unroll
                for (int nb = 0; nb < 4; ++nb) {
                    float2 v = cp[mb][half][nb];
                    v.x -= c[mb][nb][half*2];
                    v.y -= c[mb][nb][half*2 + 1];
                    *(float2*)(rowp + nb*8 + t*2) = v;
                }
            }
    } else {
        #pragma unroll
        for (int mb = 0; mb < 2; ++mb)
            #pragma unroll
            for (int half = 0; half < 2; ++half) {
                int i_loc = i0 + mb*16 + g + half*8;
                float* row = cov + (size_t)(g0 + i_loc) * LDA + g0;
                #pragma unroll
                for (int nb = 0; nb < 4; ++nb) {
                    int j = j0 + nb*8 + t*2;
                    float cx = c[mb][nb][half*2];
                    float cy = c[mb][nb][half*2 + 1];
                    if (j + 1 <= i_loc) {
                        float2 v = *(float2*)(row + j);
                        v.x -= cx; v.y -= cy;
                        *(float2*)(row + j) = v;
                    } else if (j <= i_loc) {
                        row[j] -= cx;
                    }
                }
            }
    }

    // pair 0 warp: factor + invert next step's diag1 (its own tile (0,0))
    if (pair == 0) {
        __threadfence_block();
        __syncwarp();
        float a[32];
        const float* rr = cov + (size_t)(g0 + lane) * LDA + g0;
        #pragma unroll
        for (int j = 0; j < 32; ++j)
            a[j] = (j <= lane) ? rr[j] : 0.f;
        factor_store(a, lane, Lf, rinvs,
                     g_ld + ((size_t)m * 32 + 2*(kb+1)) * 1056,
                     g_ldet + m * 32 + 2*(kb+1));
        __syncwarp();
        invert_store(lane, Lf, rinvs,
                     g_iH + ((size_t)m * 32 + 2*(kb+1)) * 1024,
                     g_iL + ((size_t)m * 32 + 2*(kb+1)) * 1024);
    }
}

// ---------------- forward substitution + output (grid: MM) ----------------
extern "C" __global__ void __launch_bounds__(512, 1)
k_finish(const float* __restrict__ y, float* __restrict__ out)
{
    __shared__ float rhs[NN];
    __shared__ float red[512];
    const int m = blockIdx.x, tid = threadIdx.x, lane = tid & 31;
    float* cov = g_cov + (size_t)m * NN * LDA;
    const float beta = g_scal[m*8+0];

    for (int i = tid; i < NN; i += 512) rhs[i] = y[i] - beta;
    __syncthreads();

    for (int kb2 = 0; kb2 < 32; ++kb2) {
        const int k0 = kb2 * 32;
        if (tid < 32) {
            const float* lrow = g_ld + ((size_t)m * 32 + kb2) * 1056 + lane * 33;
            float lr[32];
            #pragma unroll
            for (int j = 0; j < 32; ++j) lr[j] = lrow[j];
            float t = rhs[k0 + lane];
            #pragma unroll
            for (int j = 0; j < 32; ++j) {
                if (lane == j) t /= lr[j];
                float sj = __shfl_sync(0xffffffffu, t, j);
                if (lane > j) t -= sj * lr[j];
            }
            rhs[k0 + lane] = t;
        }
        __syncthreads();
        for (int i = k0 + 32 + tid; i < NN; i += 512) {
            const float* row = cov + (size_t)i * LDA + k0;
            float acc = 0.f;
            #pragma unroll
            for (int w = 0; w < 8; ++w) {
                float4 c4 = ((const float4*)row)[w];
                acc += c4.x * rhs[k0 + 4*w]     + c4.y * rhs[k0 + 4*w + 1]
                     + c4.z * rhs[k0 + 4*w + 2] + c4.w * rhs[k0 + 4*w + 3];
            }
            rhs[i] -= acc;
        }
        __syncthreads();
    }

    float q = 0.f;
    for (int i = tid; i < NN; i += 512) { float v = rhs[i]; q += v * v; }
    red[tid] = q;
    __syncthreads();
    for (int s = 256; s; s >>= 1) {
        if (tid < s) red[tid] += red[tid + s];
        __syncthreads();
    }
    if (tid == 0) {
        float ldsum = 0.f;
        for (int d = 0; d < 32; ++d) ldsum += g_ldet[m * 32 + d];
        const float LN2PI = 1.8378770664093453f;
        out[m] = -0.5f * (red[0] + 2.f * ldsum + 1024.f * LN2PI) + g_scal[m*8+5];
    }
}

extern "C" void kernel_launch(void* const* d_in, const int* in_sizes, int n_in,
                              void* d_out, int out_size)
{
    (void)in_sizes; (void)n_in; (void)out_size;
    const float* x = (const float*)d_in[0];
    const float* y = (const float*)d_in[1];
    const float* z = (const float*)d_in[2];

    k_build<<<dim3(2, MM), 512>>>(x, z,
        (const float*)d_in[3], (const float*)d_in[4],
        (const float*)d_in[5], (const float*)d_in[6],
        (const float*)d_in[7], (const float*)d_in[8],
        (const float*)d_in[9], (const float*)d_in[10],
        (const float*)d_in[11], (const float*)d_in[12]);
    k_diag0<<<MM, 32>>>();

    for (int kb = 0; kb < 16; ++kb) {
        int nt1 = 31 - 2 * kb;
        k_panel1<<<dim3((nt1 + 7) / 8, MM), 256>>>(kb);
        int nt2 = 30 - 2 * kb;
        if (nt2 > 0) {
            k_panel2<<<dim3((nt2 + 7) / 8, MM), 256>>>(kb);
            int npair = nt2 * (nt2 + 1) / 2;
            k_trail<<<dim3((npair + 7) / 8, MM), 256>>>(kb);
        }
    }
    k_finish<<<MM, 512>>>(y, (float*)d_out);
}